// round 2
// baseline (speedup 1.0000x reference)
#include <cuda_runtime.h>
#include <math.h>

#define N_NODES   100000
#define N_EDGES   1600000
#define IN_DIM    256
#define HID       64
#define CLS       32
#define NEG_SLOPE 0.01f

// ---------------- scratch (device globals; no allocations allowed) ----------
__device__ float g_Hw1[N_NODES * HID];   // 25.6 MB  layer-1 features
__device__ float g_agg[N_NODES * HID];   // 25.6 MB  layer-1 aggregate / hidden
__device__ float g_Hw2[N_NODES * CLS];   // 12.8 MB  layer-2 features
__device__ float g_s[N_NODES];           // per-node src score
__device__ float g_d[N_NODES];           // per-node dst score
__device__ float g_m[N_NODES];           // segment max
__device__ float g_den[N_NODES];         // segment sum
__device__ float g_e[N_EDGES];           // per-edge score -> exp

// ---------------- helpers ---------------------------------------------------
__device__ __forceinline__ void atomicMaxF(float* addr, float val) {
    // order-preserving int/uint trick; init must be -inf
    if (val >= 0.0f) atomicMax((int*)addr, __float_as_int(val));
    else             atomicMin((unsigned int*)addr, __float_as_uint(val));
}

// ---------------- init ------------------------------------------------------
__global__ void k_init1() {
    int i = blockIdx.x * blockDim.x + threadIdx.x;
    if (i < N_NODES * HID) g_agg[i] = 0.0f;
    if (i < N_NODES) { g_m[i] = __int_as_float(0xff800000); g_den[i] = 0.0f; }
}

__global__ void k_init2(float* __restrict__ out) {
    int i = blockIdx.x * blockDim.x + threadIdx.x;
    if (i < N_NODES * CLS) out[i] = 0.0f;
    if (i < N_NODES) { g_m[i] = __int_as_float(0xff800000); g_den[i] = 0.0f; }
}

// ---------------- layer-1 GEMM + fused attention scores ---------------------
// block = 256 threads, 4 nodes/block (64 threads per node, thread = out column)
__global__ void k_gemm1(const float* __restrict__ X,
                        const float* __restrict__ W1,
                        const float* __restrict__ A1) {
    __shared__ float Xs[4 * IN_DIM];
    __shared__ float red[8][2];
    int node0 = blockIdx.x * 4;

    for (int idx = threadIdx.x; idx < 4 * IN_DIM; idx += 256)
        Xs[idx] = X[node0 * IN_DIM + idx];
    __syncthreads();

    int r = threadIdx.x >> 6;        // 0..3 node-within-block
    int j = threadIdx.x & 63;        // 0..63 out column
    int node = node0 + r;            // N_NODES % 4 == 0 -> no bounds check

    const float4* xs4 = (const float4*)(Xs + r * IN_DIM);
    float acc = 0.0f;
#pragma unroll 8
    for (int k4 = 0; k4 < IN_DIM / 4; ++k4) {
        float4 x = xs4[k4];
        int k = k4 * 4;
        acc = fmaf(x.x, __ldg(&W1[(k + 0) * HID + j]), acc);
        acc = fmaf(x.y, __ldg(&W1[(k + 1) * HID + j]), acc);
        acc = fmaf(x.z, __ldg(&W1[(k + 2) * HID + j]), acc);
        acc = fmaf(x.w, __ldg(&W1[(k + 3) * HID + j]), acc);
    }
    g_Hw1[node * HID + j] = acc;

    // fused scores: s = H . a[:HID], d = H . a[HID:]
    float sp = acc * __ldg(&A1[j]);
    float dp = acc * __ldg(&A1[HID + j]);
#pragma unroll
    for (int off = 16; off > 0; off >>= 1) {
        sp += __shfl_down_sync(0xffffffffu, sp, off);
        dp += __shfl_down_sync(0xffffffffu, dp, off);
    }
    int w = threadIdx.x >> 5;
    if ((threadIdx.x & 31) == 0) { red[w][0] = sp; red[w][1] = dp; }
    __syncthreads();
    if (j == 0) {
        g_s[node] = red[2 * r][0] + red[2 * r + 1][0];
        g_d[node] = red[2 * r][1] + red[2 * r + 1][1];
    }
}

// ---------------- layer-2 GEMM (ELU fused) + attention scores ---------------
// block = 128 threads, warp per node, lane = out class
__global__ void k_gemm2(const float* __restrict__ W2,
                        const float* __restrict__ A2) {
    __shared__ float Hs[4][HID];
    int warp = threadIdx.x >> 5;
    int lane = threadIdx.x & 31;
    int node = blockIdx.x * 4 + warp;

    float v0 = g_agg[node * HID + lane];
    float v1 = g_agg[node * HID + 32 + lane];
    Hs[warp][lane]      = v0 > 0.0f ? v0 : expm1f(v0);
    Hs[warp][32 + lane] = v1 > 0.0f ? v1 : expm1f(v1);
    __syncwarp();

    float acc = 0.0f;
#pragma unroll
    for (int k = 0; k < HID; ++k)
        acc = fmaf(Hs[warp][k], __ldg(&W2[k * CLS + lane]), acc);
    g_Hw2[node * CLS + lane] = acc;

    float sp = acc * __ldg(&A2[lane]);
    float dp = acc * __ldg(&A2[CLS + lane]);
#pragma unroll
    for (int off = 16; off > 0; off >>= 1) {
        sp += __shfl_down_sync(0xffffffffu, sp, off);
        dp += __shfl_down_sync(0xffffffffu, dp, off);
    }
    if (lane == 0) { g_s[node] = sp; g_d[node] = dp; }
}

// ---------------- edge passes -----------------------------------------------
// edge_index is int32: src = ei[0:E], dst = ei[E:2E]
__global__ void k_edge_a(const int* __restrict__ ei) {
    int i = blockIdx.x * blockDim.x + threadIdx.x;
    if (i >= N_EDGES) return;
    int s = ei[i], d = ei[N_EDGES + i];
    float v = g_s[s] + g_d[d];
    v = v > 0.0f ? v : NEG_SLOPE * v;       // leaky_relu
    g_e[i] = v;
    atomicMaxF(&g_m[s], v);
}

__global__ void k_edge_b(const int* __restrict__ ei) {
    int i = blockIdx.x * blockDim.x + threadIdx.x;
    if (i >= N_EDGES) return;
    int s = ei[i];
    float ex = __expf(g_e[i] - g_m[s]);
    g_e[i] = ex;
    atomicAdd(&g_den[s], ex);
}

// scatter: agg[src] += att * Hw1[dst], warp per edge, 2 dims/lane
__global__ void k_agg64(const int* __restrict__ ei) {
    int gw = (blockIdx.x * blockDim.x + threadIdx.x) >> 5;
    if (gw >= N_EDGES) return;
    int lane = threadIdx.x & 31;
    int s = ei[gw], d = ei[N_EDGES + gw];
    float att = g_e[gw] / g_den[s];
    float h0 = g_Hw1[d * HID + lane];
    float h1 = g_Hw1[d * HID + 32 + lane];
    atomicAdd(&g_agg[s * HID + lane],      att * h0);
    atomicAdd(&g_agg[s * HID + 32 + lane], att * h1);
}

// scatter: out[src] += att * Hw2[dst], warp per edge, 1 dim/lane
__global__ void k_agg32(const int* __restrict__ ei, float* __restrict__ out) {
    int gw = (blockIdx.x * blockDim.x + threadIdx.x) >> 5;
    if (gw >= N_EDGES) return;
    int lane = threadIdx.x & 31;
    int s = ei[gw], d = ei[N_EDGES + gw];
    float att = g_e[gw] / g_den[s];
    atomicAdd(&out[s * CLS + lane], att * g_Hw2[d * CLS + lane]);
}

// ---------------- log_softmax (warp per node) --------------------------------
__global__ void k_lsm(float* __restrict__ out) {
    int gw = (blockIdx.x * blockDim.x + threadIdx.x) >> 5;
    if (gw >= N_NODES) return;
    int lane = threadIdx.x & 31;
    float x = out[gw * CLS + lane];
    float mx = x;
#pragma unroll
    for (int off = 16; off > 0; off >>= 1)
        mx = fmaxf(mx, __shfl_xor_sync(0xffffffffu, mx, off));
    float ex = __expf(x - mx);
    float sm = ex;
#pragma unroll
    for (int off = 16; off > 0; off >>= 1)
        sm += __shfl_xor_sync(0xffffffffu, sm, off);
    out[gw * CLS + lane] = x - mx - __logf(sm);
}

// ---------------- launch -----------------------------------------------------
extern "C" void kernel_launch(void* const* d_in, const int* in_sizes, int n_in,
                              void* d_out, int out_size) {
    const float* X  = (const float*)d_in[0];
    const int*   EI = (const int*)d_in[1];     // int32 (JAX default: x64 disabled)
    const float* W1 = (const float*)d_in[2];
    const float* W2 = (const float*)d_in[3];
    const float* A1 = (const float*)d_in[4];
    const float* A2 = (const float*)d_in[5];
    float* out = (float*)d_out;

    const int T = 256;
    int g_init1 = (N_NODES * HID + T - 1) / T;
    int g_edges = (N_EDGES + T - 1) / T;
    int g_warp_edges = (int)(((long long)N_EDGES * 32 + T - 1) / T);
    int g_init2 = (N_NODES * CLS + T - 1) / T;
    int g_lsm = (N_NODES * 32 + T - 1) / T;

    // layer 1
    k_init1<<<g_init1, T>>>();
    k_gemm1<<<N_NODES / 4, 256>>>(X, W1, A1);
    k_edge_a<<<g_edges, T>>>(EI);
    k_edge_b<<<g_edges, T>>>(EI);
    k_agg64<<<g_warp_edges, T>>>(EI);

    // layer 2
    k_init2<<<g_init2, T>>>(out);
    k_gemm2<<<N_NODES / 4, 128>>>(W2, A2);
    k_edge_a<<<g_edges, T>>>(EI);
    k_edge_b<<<g_edges, T>>>(EI);
    k_agg32<<<g_warp_edges, T>>>(EI, out);

    // epilogue
    k_lsm<<<g_lsm, T>>>(out);
}

// round 3
// speedup vs baseline: 1.6928x; 1.6928x over previous
#include <cuda_runtime.h>
#include <math.h>

#define N_NODES   100000
#define N_EDGES   1600000
#define IN_DIM    256
#define HID       64
#define CLS       32
#define NEG_SLOPE 0.01f

// ---------------- scratch (device globals; no allocations allowed) ----------
__device__ float g_Hw1[N_NODES * HID];   // 25.6 MB  layer-1 features
__device__ float g_agg[N_NODES * HID];   // 25.6 MB  layer-1 aggregate / hidden
__device__ float g_Hw2[N_NODES * CLS];   // 12.8 MB  layer-2 features
__device__ float g_s[N_NODES];           // per-node src score
__device__ float g_d[N_NODES];           // per-node dst score
__device__ float g_m[N_NODES];           // segment max
__device__ float g_den[N_NODES];         // segment sum
__device__ float g_e[N_EDGES];           // per-edge score -> exp

// ---------------- helpers ---------------------------------------------------
__device__ __forceinline__ void atomicMaxF(float* addr, float val) {
    if (val >= 0.0f) atomicMax((int*)addr, __float_as_int(val));
    else             atomicMin((unsigned int*)addr, __float_as_uint(val));
}

__device__ __forceinline__ void red_add_v4(float* addr, float a, float b, float c, float d) {
    asm volatile("red.global.add.v4.f32 [%0], {%1, %2, %3, %4};"
                 :: "l"(addr), "f"(a), "f"(b), "f"(c), "f"(d) : "memory");
}

// ---------------- init ------------------------------------------------------
__global__ void k_init1() {
    int i = blockIdx.x * blockDim.x + threadIdx.x;
    if (i < N_NODES * HID) g_agg[i] = 0.0f;
    if (i < N_NODES) { g_m[i] = __int_as_float(0xff800000); g_den[i] = 0.0f; }
}

__global__ void k_init2(float* __restrict__ out) {
    int i = blockIdx.x * blockDim.x + threadIdx.x;
    if (i < N_NODES * CLS) out[i] = 0.0f;
    if (i < N_NODES) { g_m[i] = __int_as_float(0xff800000); g_den[i] = 0.0f; }
}

// ---------------- layer-1 GEMM + fused attention scores ---------------------
// block = 256 threads; 16 nodes/block.
// thread: j = out column (0..63), rg = node-quad (0..3); 4 nodes per thread,
// so every W1 load is reused by 4 FMAs (4x fewer LDGs than 1 node/thread).
__global__ void k_gemm1(const float* __restrict__ X,
                        const float* __restrict__ W1,
                        const float* __restrict__ A1) {
    __shared__ float Xs[16 * IN_DIM];          // 16 KB
    __shared__ float red[8][4][2];
    int node0 = blockIdx.x * 16;

    for (int idx = threadIdx.x * 4; idx < 16 * IN_DIM; idx += 256 * 4)
        *(float4*)(Xs + idx) = *(const float4*)(X + node0 * IN_DIM + idx);
    __syncthreads();

    int j  = threadIdx.x & 63;
    int rg = threadIdx.x >> 6;                 // 0..3

    const float4* xs0 = (const float4*)(Xs + (rg * 4 + 0) * IN_DIM);
    const float4* xs1 = (const float4*)(Xs + (rg * 4 + 1) * IN_DIM);
    const float4* xs2 = (const float4*)(Xs + (rg * 4 + 2) * IN_DIM);
    const float4* xs3 = (const float4*)(Xs + (rg * 4 + 3) * IN_DIM);

    float acc0 = 0.f, acc1 = 0.f, acc2 = 0.f, acc3 = 0.f;
#pragma unroll 8
    for (int k4 = 0; k4 < IN_DIM / 4; ++k4) {
        int k = k4 * 4;
        float w0 = __ldg(&W1[(k + 0) * HID + j]);
        float w1 = __ldg(&W1[(k + 1) * HID + j]);
        float w2 = __ldg(&W1[(k + 2) * HID + j]);
        float w3 = __ldg(&W1[(k + 3) * HID + j]);
        float4 x0 = xs0[k4], x1 = xs1[k4], x2 = xs2[k4], x3 = xs3[k4];
        acc0 = fmaf(x0.x, w0, acc0); acc0 = fmaf(x0.y, w1, acc0);
        acc0 = fmaf(x0.z, w2, acc0); acc0 = fmaf(x0.w, w3, acc0);
        acc1 = fmaf(x1.x, w0, acc1); acc1 = fmaf(x1.y, w1, acc1);
        acc1 = fmaf(x1.z, w2, acc1); acc1 = fmaf(x1.w, w3, acc1);
        acc2 = fmaf(x2.x, w0, acc2); acc2 = fmaf(x2.y, w1, acc2);
        acc2 = fmaf(x2.z, w2, acc2); acc2 = fmaf(x2.w, w3, acc2);
        acc3 = fmaf(x3.x, w0, acc3); acc3 = fmaf(x3.y, w1, acc3);
        acc3 = fmaf(x3.z, w2, acc3); acc3 = fmaf(x3.w, w3, acc3);
    }

    int nb = node0 + rg * 4;
    g_Hw1[(nb + 0) * HID + j] = acc0;
    g_Hw1[(nb + 1) * HID + j] = acc1;
    g_Hw1[(nb + 2) * HID + j] = acc2;
    g_Hw1[(nb + 3) * HID + j] = acc3;

    // fused per-node scores: s = H . A1[:HID], d = H . A1[HID:]
    float a_s = __ldg(&A1[j]), a_d = __ldg(&A1[HID + j]);
    float s0 = acc0 * a_s, d0 = acc0 * a_d;
    float s1 = acc1 * a_s, d1 = acc1 * a_d;
    float s2 = acc2 * a_s, d2 = acc2 * a_d;
    float s3 = acc3 * a_s, d3 = acc3 * a_d;
#pragma unroll
    for (int off = 16; off > 0; off >>= 1) {
        s0 += __shfl_down_sync(0xffffffffu, s0, off);
        d0 += __shfl_down_sync(0xffffffffu, d0, off);
        s1 += __shfl_down_sync(0xffffffffu, s1, off);
        d1 += __shfl_down_sync(0xffffffffu, d1, off);
        s2 += __shfl_down_sync(0xffffffffu, s2, off);
        d2 += __shfl_down_sync(0xffffffffu, d2, off);
        s3 += __shfl_down_sync(0xffffffffu, s3, off);
        d3 += __shfl_down_sync(0xffffffffu, d3, off);
    }
    int w = threadIdx.x >> 5;
    if ((threadIdx.x & 31) == 0) {
        red[w][0][0] = s0; red[w][0][1] = d0;
        red[w][1][0] = s1; red[w][1][1] = d1;
        red[w][2][0] = s2; red[w][2][1] = d2;
        red[w][3][0] = s3; red[w][3][1] = d3;
    }
    __syncthreads();
    if (j == 0) {
#pragma unroll
        for (int i = 0; i < 4; ++i) {
            g_s[nb + i] = red[rg * 2][i][0] + red[rg * 2 + 1][i][0];
            g_d[nb + i] = red[rg * 2][i][1] + red[rg * 2 + 1][i][1];
        }
    }
}

// ---------------- layer-2 GEMM (ELU fused) + attention scores ---------------
__global__ void k_gemm2(const float* __restrict__ W2,
                        const float* __restrict__ A2) {
    __shared__ float Hs[4][HID];
    int warp = threadIdx.x >> 5;
    int lane = threadIdx.x & 31;
    int node = blockIdx.x * 4 + warp;

    float v0 = g_agg[node * HID + lane];
    float v1 = g_agg[node * HID + 32 + lane];
    Hs[warp][lane]      = v0 > 0.0f ? v0 : expm1f(v0);
    Hs[warp][32 + lane] = v1 > 0.0f ? v1 : expm1f(v1);
    __syncwarp();

    float acc = 0.0f;
#pragma unroll
    for (int k = 0; k < HID; ++k)
        acc = fmaf(Hs[warp][k], __ldg(&W2[k * CLS + lane]), acc);
    g_Hw2[node * CLS + lane] = acc;

    float sp = acc * __ldg(&A2[lane]);
    float dp = acc * __ldg(&A2[CLS + lane]);
#pragma unroll
    for (int off = 16; off > 0; off >>= 1) {
        sp += __shfl_down_sync(0xffffffffu, sp, off);
        dp += __shfl_down_sync(0xffffffffu, dp, off);
    }
    if (lane == 0) { g_s[node] = sp; g_d[node] = dp; }
}

// ---------------- edge passes -----------------------------------------------
// edge_index is int32: src = ei[0:E], dst = ei[E:2E]
__global__ void k_edge_a(const int* __restrict__ ei) {
    int i = blockIdx.x * blockDim.x + threadIdx.x;
    if (i >= N_EDGES) return;
    int s = ei[i], d = ei[N_EDGES + i];
    float v = g_s[s] + g_d[d];
    v = v > 0.0f ? v : NEG_SLOPE * v;
    g_e[i] = v;
    atomicMaxF(&g_m[s], v);
}

__global__ void k_edge_b(const int* __restrict__ ei) {
    int i = blockIdx.x * blockDim.x + threadIdx.x;
    if (i >= N_EDGES) return;
    int s = ei[i];
    float ex = __expf(g_e[i] - g_m[s]);
    g_e[i] = ex;
    atomicAdd(&g_den[s], ex);
}

// scatter: agg[src] += att * Hw1[dst]; 16 lanes/edge, v4 REDs (4x fewer ops)
__global__ void k_agg64(const int* __restrict__ ei) {
    int idx = blockIdx.x * blockDim.x + threadIdx.x;
    int e = idx >> 4;
    if (e >= N_EDGES) return;
    int l = idx & 15;
    int s = ei[e], d = ei[N_EDGES + e];
    float att = g_e[e] / g_den[s];
    float4 h = *(const float4*)(g_Hw1 + d * HID + l * 4);
    red_add_v4(&g_agg[s * HID + l * 4], att * h.x, att * h.y, att * h.z, att * h.w);
}

// scatter: out[src] += att * Hw2[dst]; 8 lanes/edge, v4 REDs
__global__ void k_agg32(const int* __restrict__ ei, float* __restrict__ out) {
    int idx = blockIdx.x * blockDim.x + threadIdx.x;
    int e = idx >> 3;
    if (e >= N_EDGES) return;
    int l = idx & 7;
    int s = ei[e], d = ei[N_EDGES + e];
    float att = g_e[e] / g_den[s];
    float4 h = *(const float4*)(g_Hw2 + d * CLS + l * 4);
    red_add_v4(&out[s * CLS + l * 4], att * h.x, att * h.y, att * h.z, att * h.w);
}

// ---------------- log_softmax (warp per node) --------------------------------
__global__ void k_lsm(float* __restrict__ out) {
    int gw = (blockIdx.x * blockDim.x + threadIdx.x) >> 5;
    if (gw >= N_NODES) return;
    int lane = threadIdx.x & 31;
    float x = out[gw * CLS + lane];
    float mx = x;
#pragma unroll
    for (int off = 16; off > 0; off >>= 1)
        mx = fmaxf(mx, __shfl_xor_sync(0xffffffffu, mx, off));
    float ex = __expf(x - mx);
    float sm = ex;
#pragma unroll
    for (int off = 16; off > 0; off >>= 1)
        sm += __shfl_xor_sync(0xffffffffu, sm, off);
    out[gw * CLS + lane] = x - mx - __logf(sm);
}

// ---------------- launch -----------------------------------------------------
extern "C" void kernel_launch(void* const* d_in, const int* in_sizes, int n_in,
                              void* d_out, int out_size) {
    const float* X  = (const float*)d_in[0];
    const int*   EI = (const int*)d_in[1];     // int32 (JAX default: x64 disabled)
    const float* W1 = (const float*)d_in[2];
    const float* W2 = (const float*)d_in[3];
    const float* A1 = (const float*)d_in[4];
    const float* A2 = (const float*)d_in[5];
    float* out = (float*)d_out;

    const int T = 256;
    int g_init1 = (N_NODES * HID + T - 1) / T;
    int g_edges = (N_EDGES + T - 1) / T;
    int g_agg64 = (int)(((long long)N_EDGES * 16 + T - 1) / T);
    int g_agg32g = (int)(((long long)N_EDGES * 8 + T - 1) / T);
    int g_init2 = (N_NODES * CLS + T - 1) / T;
    int g_lsm = (N_NODES * 32 + T - 1) / T;

    // layer 1
    k_init1<<<g_init1, T>>>();
    k_gemm1<<<N_NODES / 16, 256>>>(X, W1, A1);
    k_edge_a<<<g_edges, T>>>(EI);
    k_edge_b<<<g_edges, T>>>(EI);
    k_agg64<<<g_agg64, T>>>(EI);

    // layer 2
    k_init2<<<g_init2, T>>>(out);
    k_gemm2<<<N_NODES / 4, 128>>>(W2, A2);
    k_edge_a<<<g_edges, T>>>(EI);
    k_edge_b<<<g_edges, T>>>(EI);
    k_agg32<<<g_agg32g, T>>>(EI, out);

    // epilogue
    k_lsm<<<g_lsm, T>>>(out);
}

// round 4
// speedup vs baseline: 2.0125x; 1.1888x over previous
#include <cuda_runtime.h>
#include <math.h>

#define N_NODES   100000
#define N_EDGES   1600000
#define IN_DIM    256
#define HID       64
#define CLS       32
#define NEG_SLOPE 0.01f
#define NBLK_SCAN ((N_NODES + 255) / 256)   // 391

// ---------------- scratch (device globals; no allocations allowed) ----------
__device__ float g_Hw1[N_NODES * HID];   // layer-1 features
__device__ float g_agg[N_NODES * HID];   // elu(aggregate) = hidden
__device__ float g_Hw2[N_NODES * CLS];   // layer-2 features
__device__ float g_s[N_NODES];
__device__ float g_d[N_NODES];
__device__ float g_ecsr[N_EDGES];        // edge scores in CSR order
__device__ int   g_deg[N_NODES];
__device__ int   g_off[N_NODES + 1];
__device__ int   g_pos[N_NODES];
__device__ int   g_csr_dst[N_EDGES];     // dst per CSR slot
__device__ int   g_slot[N_EDGES];        // edge id -> CSR slot
__device__ int   g_bsum[NBLK_SCAN];
__device__ int   g_bscan[NBLK_SCAN];

// ================= CSR build =================================================
__global__ void k_zero() {
    int i = blockIdx.x * blockDim.x + threadIdx.x;
    if (i < N_NODES) { g_deg[i] = 0; g_pos[i] = 0; }
}

__global__ void k_count(const int* __restrict__ ei) {
    int i = blockIdx.x * blockDim.x + threadIdx.x;
    if (i < N_EDGES) atomicAdd(&g_deg[ei[i]], 1);
}

// per-block exclusive scan of 256 degrees
__global__ void k_scan1() {
    __shared__ int sh[256];
    int t = threadIdx.x;
    int i = blockIdx.x * 256 + t;
    int v = (i < N_NODES) ? g_deg[i] : 0;
    sh[t] = v;
    __syncthreads();
#pragma unroll
    for (int o = 1; o < 256; o <<= 1) {
        int x = (t >= o) ? sh[t - o] : 0;
        __syncthreads();
        sh[t] += x;
        __syncthreads();
    }
    if (i < N_NODES) g_off[i] = sh[t] - v;          // exclusive within block
    if (t == 255) g_bsum[blockIdx.x] = sh[255];
}

// scan of block sums (391 -> pad 512), single block
__global__ void k_scan2() {
    __shared__ int sh[512];
    int t = threadIdx.x;
    int v = (t < NBLK_SCAN) ? g_bsum[t] : 0;
    sh[t] = v;
    __syncthreads();
#pragma unroll
    for (int o = 1; o < 512; o <<= 1) {
        int x = (t >= o) ? sh[t - o] : 0;
        __syncthreads();
        sh[t] += x;
        __syncthreads();
    }
    if (t < NBLK_SCAN) g_bscan[t] = sh[t] - v;      // exclusive
}

__global__ void k_scan3() {
    int i = blockIdx.x * blockDim.x + threadIdx.x;
    if (i < N_NODES) g_off[i] += g_bscan[i >> 8];
    if (i == 0) g_off[N_NODES] = N_EDGES;
}

__global__ void k_fill(const int* __restrict__ ei) {
    int i = blockIdx.x * blockDim.x + threadIdx.x;
    if (i >= N_EDGES) return;
    int s = ei[i];
    int slot = g_off[s] + atomicAdd(&g_pos[s], 1);
    g_csr_dst[slot] = ei[N_EDGES + i];
    g_slot[i] = slot;
}

// ================= layer GEMMs ==============================================
// block = 256 threads; 16 nodes/block; 4 nodes per thread (W1 reuse x4)
__global__ void k_gemm1(const float* __restrict__ X,
                        const float* __restrict__ W1,
                        const float* __restrict__ A1) {
    __shared__ float Xs[16 * IN_DIM];
    __shared__ float red[8][4][2];
    int node0 = blockIdx.x * 16;

    for (int idx = threadIdx.x * 4; idx < 16 * IN_DIM; idx += 256 * 4)
        *(float4*)(Xs + idx) = *(const float4*)(X + node0 * IN_DIM + idx);
    __syncthreads();

    int j  = threadIdx.x & 63;
    int rg = threadIdx.x >> 6;

    const float4* xs0 = (const float4*)(Xs + (rg * 4 + 0) * IN_DIM);
    const float4* xs1 = (const float4*)(Xs + (rg * 4 + 1) * IN_DIM);
    const float4* xs2 = (const float4*)(Xs + (rg * 4 + 2) * IN_DIM);
    const float4* xs3 = (const float4*)(Xs + (rg * 4 + 3) * IN_DIM);

    float acc0 = 0.f, acc1 = 0.f, acc2 = 0.f, acc3 = 0.f;
#pragma unroll 8
    for (int k4 = 0; k4 < IN_DIM / 4; ++k4) {
        int k = k4 * 4;
        float w0 = __ldg(&W1[(k + 0) * HID + j]);
        float w1 = __ldg(&W1[(k + 1) * HID + j]);
        float w2 = __ldg(&W1[(k + 2) * HID + j]);
        float w3 = __ldg(&W1[(k + 3) * HID + j]);
        float4 x0 = xs0[k4], x1 = xs1[k4], x2 = xs2[k4], x3 = xs3[k4];
        acc0 = fmaf(x0.x, w0, acc0); acc0 = fmaf(x0.y, w1, acc0);
        acc0 = fmaf(x0.z, w2, acc0); acc0 = fmaf(x0.w, w3, acc0);
        acc1 = fmaf(x1.x, w0, acc1); acc1 = fmaf(x1.y, w1, acc1);
        acc1 = fmaf(x1.z, w2, acc1); acc1 = fmaf(x1.w, w3, acc1);
        acc2 = fmaf(x2.x, w0, acc2); acc2 = fmaf(x2.y, w1, acc2);
        acc2 = fmaf(x2.z, w2, acc2); acc2 = fmaf(x2.w, w3, acc2);
        acc3 = fmaf(x3.x, w0, acc3); acc3 = fmaf(x3.y, w1, acc3);
        acc3 = fmaf(x3.z, w2, acc3); acc3 = fmaf(x3.w, w3, acc3);
    }

    int nb = node0 + rg * 4;
    g_Hw1[(nb + 0) * HID + j] = acc0;
    g_Hw1[(nb + 1) * HID + j] = acc1;
    g_Hw1[(nb + 2) * HID + j] = acc2;
    g_Hw1[(nb + 3) * HID + j] = acc3;

    float a_s = __ldg(&A1[j]), a_d = __ldg(&A1[HID + j]);
    float s0 = acc0 * a_s, d0 = acc0 * a_d;
    float s1 = acc1 * a_s, d1 = acc1 * a_d;
    float s2 = acc2 * a_s, d2 = acc2 * a_d;
    float s3 = acc3 * a_s, d3 = acc3 * a_d;
#pragma unroll
    for (int off = 16; off > 0; off >>= 1) {
        s0 += __shfl_down_sync(0xffffffffu, s0, off);
        d0 += __shfl_down_sync(0xffffffffu, d0, off);
        s1 += __shfl_down_sync(0xffffffffu, s1, off);
        d1 += __shfl_down_sync(0xffffffffu, d1, off);
        s2 += __shfl_down_sync(0xffffffffu, s2, off);
        d2 += __shfl_down_sync(0xffffffffu, d2, off);
        s3 += __shfl_down_sync(0xffffffffu, s3, off);
        d3 += __shfl_down_sync(0xffffffffu, d3, off);
    }
    int w = threadIdx.x >> 5;
    if ((threadIdx.x & 31) == 0) {
        red[w][0][0] = s0; red[w][0][1] = d0;
        red[w][1][0] = s1; red[w][1][1] = d1;
        red[w][2][0] = s2; red[w][2][1] = d2;
        red[w][3][0] = s3; red[w][3][1] = d3;
    }
    __syncthreads();
    if (j == 0) {
#pragma unroll
        for (int i = 0; i < 4; ++i) {
            g_s[nb + i] = red[rg * 2][i][0] + red[rg * 2 + 1][i][0];
            g_d[nb + i] = red[rg * 2][i][1] + red[rg * 2 + 1][i][1];
        }
    }
}

// layer-2 GEMM (hidden already has ELU applied); warp per node
__global__ void k_gemm2(const float* __restrict__ W2,
                        const float* __restrict__ A2) {
    __shared__ float Hs[4][HID];
    int warp = threadIdx.x >> 5;
    int lane = threadIdx.x & 31;
    int node = blockIdx.x * 4 + warp;

    Hs[warp][lane]      = g_agg[node * HID + lane];
    Hs[warp][32 + lane] = g_agg[node * HID + 32 + lane];
    __syncwarp();

    float acc = 0.0f;
#pragma unroll
    for (int k = 0; k < HID; ++k)
        acc = fmaf(Hs[warp][k], __ldg(&W2[k * CLS + lane]), acc);
    g_Hw2[node * CLS + lane] = acc;

    float sp = acc * __ldg(&A2[lane]);
    float dp = acc * __ldg(&A2[CLS + lane]);
#pragma unroll
    for (int off = 16; off > 0; off >>= 1) {
        sp += __shfl_down_sync(0xffffffffu, sp, off);
        dp += __shfl_down_sync(0xffffffffu, dp, off);
    }
    if (lane == 0) { g_s[node] = sp; g_d[node] = dp; }
}

// ================= edge score (into CSR order, no atomics) ===================
__global__ void k_escore(const int* __restrict__ ei) {
    int i = blockIdx.x * blockDim.x + threadIdx.x;
    if (i >= N_EDGES) return;
    float v = g_s[ei[i]] + g_d[ei[N_EDGES + i]];
    v = v > 0.0f ? v : NEG_SLOPE * v;
    g_ecsr[g_slot[i]] = v;
}

// ================= softmax + aggregate (warp per node, gather) ===============
// layer 1: D=64, epilogue = ELU, writes g_agg
__global__ void k_softagg64() {
    int n = blockIdx.x * 8 + (threadIdx.x >> 5);
    int lane = threadIdx.x & 31;
    int beg = g_off[n], end = g_off[n + 1];

    float m = -__int_as_float(0x7f800000) * 0.f - 1e30f;
    m = -1e30f;
    for (int k = beg + lane; k < end; k += 32) m = fmaxf(m, g_ecsr[k]);
#pragma unroll
    for (int o = 16; o > 0; o >>= 1) m = fmaxf(m, __shfl_xor_sync(0xffffffffu, m, o));

    float den = 0.f;
    for (int k = beg + lane; k < end; k += 32) den += __expf(g_ecsr[k] - m);
#pragma unroll
    for (int o = 16; o > 0; o >>= 1) den += __shfl_xor_sync(0xffffffffu, den, o);
    float inv = (end > beg) ? 1.0f / den : 0.0f;

    float2 acc = make_float2(0.f, 0.f);
    for (int k = beg; k < end; ++k) {
        int   d   = g_csr_dst[k];                     // broadcast
        float att = __expf(g_ecsr[k] - m) * inv;      // broadcast
        float2 h = *(const float2*)(g_Hw1 + d * HID + lane * 2);
        acc.x = fmaf(att, h.x, acc.x);
        acc.y = fmaf(att, h.y, acc.y);
    }
    // fused ELU
    acc.x = acc.x > 0.f ? acc.x : expm1f(acc.x);
    acc.y = acc.y > 0.f ? acc.y : expm1f(acc.y);
    *(float2*)(g_agg + n * HID + lane * 2) = acc;
}

// layer 2: D=32, epilogue = log_softmax, writes final out
__global__ void k_softagg32(float* __restrict__ out) {
    int n = blockIdx.x * 8 + (threadIdx.x >> 5);
    int lane = threadIdx.x & 31;
    int beg = g_off[n], end = g_off[n + 1];

    float m = -1e30f;
    for (int k = beg + lane; k < end; k += 32) m = fmaxf(m, g_ecsr[k]);
#pragma unroll
    for (int o = 16; o > 0; o >>= 1) m = fmaxf(m, __shfl_xor_sync(0xffffffffu, m, o));

    float den = 0.f;
    for (int k = beg + lane; k < end; k += 32) den += __expf(g_ecsr[k] - m);
#pragma unroll
    for (int o = 16; o > 0; o >>= 1) den += __shfl_xor_sync(0xffffffffu, den, o);
    float inv = (end > beg) ? 1.0f / den : 0.0f;

    float acc = 0.f;
    for (int k = beg; k < end; ++k) {
        int   d   = g_csr_dst[k];
        float att = __expf(g_ecsr[k] - m) * inv;
        acc = fmaf(att, g_Hw2[d * CLS + lane], acc);
    }
    // fused log_softmax over the 32 classes (one per lane)
    float mx = acc;
#pragma unroll
    for (int o = 16; o > 0; o >>= 1) mx = fmaxf(mx, __shfl_xor_sync(0xffffffffu, mx, o));
    float ex = __expf(acc - mx);
    float sm = ex;
#pragma unroll
    for (int o = 16; o > 0; o >>= 1) sm += __shfl_xor_sync(0xffffffffu, sm, o);
    out[n * CLS + lane] = acc - mx - __logf(sm);
}

// ================= launch ====================================================
extern "C" void kernel_launch(void* const* d_in, const int* in_sizes, int n_in,
                              void* d_out, int out_size) {
    const float* X  = (const float*)d_in[0];
    const int*   EI = (const int*)d_in[1];     // int32 (JAX x64 disabled)
    const float* W1 = (const float*)d_in[2];
    const float* W2 = (const float*)d_in[3];
    const float* A1 = (const float*)d_in[4];
    const float* A2 = (const float*)d_in[5];
    float* out = (float*)d_out;

    const int T = 256;
    int g_nodes = (N_NODES + T - 1) / T;       // 391
    int g_edges = (N_EDGES + T - 1) / T;       // 6250

    // CSR build (once; both layers share the graph)
    k_zero<<<g_nodes, T>>>();
    k_count<<<g_edges, T>>>(EI);
    k_scan1<<<NBLK_SCAN, 256>>>();
    k_scan2<<<1, 512>>>();
    k_scan3<<<g_nodes, T>>>();
    k_fill<<<g_edges, T>>>(EI);

    // layer 1
    k_gemm1<<<N_NODES / 16, 256>>>(X, W1, A1);
    k_escore<<<g_edges, T>>>(EI);
    k_softagg64<<<N_NODES / 8, 256>>>();

    // layer 2
    k_gemm2<<<N_NODES / 4, 128>>>(W2, A2);
    k_escore<<<g_edges, T>>>(EI);
    k_softagg32<<<N_NODES / 8, 256>>>(out);
}

// round 5
// speedup vs baseline: 2.2200x; 1.1031x over previous
#include <cuda_runtime.h>
#include <math.h>

#define N_NODES   100000
#define N_EDGES   1600000
#define IN_DIM    256
#define HID       64
#define CLS       32
#define NEG_SLOPE 0.01f
#define NBLK_SCAN ((N_NODES + 255) / 256)   // 391

// ---------------- scratch (device globals; no allocations allowed) ----------
__device__ float g_Hw1[N_NODES * HID];   // layer-1 features
__device__ float g_agg[N_NODES * HID];   // elu(aggregate) = hidden
__device__ float g_Hw2[N_NODES * CLS];   // layer-2 features
__device__ float g_s[N_NODES];
__device__ float g_d[N_NODES];
__device__ int   g_deg[N_NODES];
__device__ int   g_off[N_NODES + 1];
__device__ int   g_pos[N_NODES];
__device__ int   g_csr_dst[N_EDGES];     // dst per CSR slot
__device__ int   g_bsum[NBLK_SCAN];
__device__ int   g_bscan[NBLK_SCAN];

// ================= CSR build =================================================
__global__ void k_zero() {
    int i = blockIdx.x * blockDim.x + threadIdx.x;
    if (i < N_NODES) { g_deg[i] = 0; g_pos[i] = 0; }
}

__global__ void k_count(const int* __restrict__ ei) {
    int i = blockIdx.x * blockDim.x + threadIdx.x;
    if (i < N_EDGES) atomicAdd(&g_deg[ei[i]], 1);
}

__global__ void k_scan1() {
    __shared__ int sh[256];
    int t = threadIdx.x;
    int i = blockIdx.x * 256 + t;
    int v = (i < N_NODES) ? g_deg[i] : 0;
    sh[t] = v;
    __syncthreads();
#pragma unroll
    for (int o = 1; o < 256; o <<= 1) {
        int x = (t >= o) ? sh[t - o] : 0;
        __syncthreads();
        sh[t] += x;
        __syncthreads();
    }
    if (i < N_NODES) g_off[i] = sh[t] - v;
    if (t == 255) g_bsum[blockIdx.x] = sh[255];
}

__global__ void k_scan2() {
    __shared__ int sh[512];
    int t = threadIdx.x;
    int v = (t < NBLK_SCAN) ? g_bsum[t] : 0;
    sh[t] = v;
    __syncthreads();
#pragma unroll
    for (int o = 1; o < 512; o <<= 1) {
        int x = (t >= o) ? sh[t - o] : 0;
        __syncthreads();
        sh[t] += x;
        __syncthreads();
    }
    if (t < NBLK_SCAN) g_bscan[t] = sh[t] - v;
}

__global__ void k_scan3() {
    int i = blockIdx.x * blockDim.x + threadIdx.x;
    if (i < N_NODES) g_off[i] += g_bscan[i >> 8];
    if (i == 0) g_off[N_NODES] = N_EDGES;
}

__global__ void k_fill(const int* __restrict__ ei) {
    int i = blockIdx.x * blockDim.x + threadIdx.x;
    if (i >= N_EDGES) return;
    int s = ei[i];
    int slot = g_off[s] + atomicAdd(&g_pos[s], 1);
    g_csr_dst[slot] = ei[N_EDGES + i];
}

// ================= layer-1 GEMM + fused scores ==============================
// block = 256 threads; 32 nodes/block; 8 nodes per thread (W1 LDG reuse x8)
__global__ void k_gemm1(const float* __restrict__ X,
                        const float* __restrict__ W1,
                        const float* __restrict__ A1) {
    __shared__ float Xs[32 * IN_DIM];          // 32 KB
    __shared__ float red[8][8][2];
    int node0 = blockIdx.x * 32;

    for (int idx = threadIdx.x * 4; idx < 32 * IN_DIM; idx += 256 * 4)
        *(float4*)(Xs + idx) = *(const float4*)(X + node0 * IN_DIM + idx);
    __syncthreads();

    int j  = threadIdx.x & 63;
    int rg = threadIdx.x >> 6;                 // 0..3 -> 8 nodes each

    float acc[8];
#pragma unroll
    for (int r = 0; r < 8; ++r) acc[r] = 0.f;

#pragma unroll 4
    for (int k4 = 0; k4 < IN_DIM / 4; ++k4) {
        int k = k4 * 4;
        float w0 = __ldg(&W1[(k + 0) * HID + j]);
        float w1 = __ldg(&W1[(k + 1) * HID + j]);
        float w2 = __ldg(&W1[(k + 2) * HID + j]);
        float w3 = __ldg(&W1[(k + 3) * HID + j]);
#pragma unroll
        for (int r = 0; r < 8; ++r) {
            float4 x = *(const float4*)(Xs + (rg * 8 + r) * IN_DIM + k);
            acc[r] = fmaf(x.x, w0, acc[r]);
            acc[r] = fmaf(x.y, w1, acc[r]);
            acc[r] = fmaf(x.z, w2, acc[r]);
            acc[r] = fmaf(x.w, w3, acc[r]);
        }
    }

    int nb = node0 + rg * 8;
#pragma unroll
    for (int r = 0; r < 8; ++r) g_Hw1[(nb + r) * HID + j] = acc[r];

    float a_s = __ldg(&A1[j]), a_d = __ldg(&A1[HID + j]);
    int w = threadIdx.x >> 5;
#pragma unroll
    for (int r = 0; r < 8; ++r) {
        float sp = acc[r] * a_s;
        float dp = acc[r] * a_d;
#pragma unroll
        for (int o = 16; o > 0; o >>= 1) {
            sp += __shfl_down_sync(0xffffffffu, sp, o);
            dp += __shfl_down_sync(0xffffffffu, dp, o);
        }
        if ((threadIdx.x & 31) == 0) { red[w][r][0] = sp; red[w][r][1] = dp; }
    }
    __syncthreads();
    if (j == 0) {
#pragma unroll
        for (int r = 0; r < 8; ++r) {
            g_s[nb + r] = red[rg * 2][r][0] + red[rg * 2 + 1][r][0];
            g_d[nb + r] = red[rg * 2][r][1] + red[rg * 2 + 1][r][1];
        }
    }
}

// ================= layer-2 GEMM + fused scores ==============================
__global__ void k_gemm2(const float* __restrict__ W2,
                        const float* __restrict__ A2) {
    __shared__ float Hs[4][HID];
    int warp = threadIdx.x >> 5;
    int lane = threadIdx.x & 31;
    int node = blockIdx.x * 4 + warp;

    Hs[warp][lane]      = g_agg[node * HID + lane];
    Hs[warp][32 + lane] = g_agg[node * HID + 32 + lane];
    __syncwarp();

    float acc = 0.0f;
#pragma unroll
    for (int k = 0; k < HID; ++k)
        acc = fmaf(Hs[warp][k], __ldg(&W2[k * CLS + lane]), acc);
    g_Hw2[node * CLS + lane] = acc;

    float sp = acc * __ldg(&A2[lane]);
    float dp = acc * __ldg(&A2[CLS + lane]);
#pragma unroll
    for (int o = 16; o > 0; o >>= 1) {
        sp += __shfl_down_sync(0xffffffffu, sp, o);
        dp += __shfl_down_sync(0xffffffffu, dp, o);
    }
    if (lane == 0) { g_s[node] = sp; g_d[node] = dp; }
}

// ================= softmax + aggregate (warp/node, online softmax) ==========
// Scores recomputed inline: e = leaky(s[n] + d[dst]). No edge-score arrays.
// layer 1: D=64 (float2/lane), epilogue ELU -> g_agg
__global__ void k_softagg64() {
    int n = blockIdx.x * 8 + (threadIdx.x >> 5);
    int lane = threadIdx.x & 31;
    int beg = g_off[n], end = g_off[n + 1];
    float sn = g_s[n];

    // online softmax stats (per-lane, then shfl merge)
    float m = -1e30f, den = 0.f;
    for (int k = beg + lane; k < end; k += 32) {
        float e = sn + g_d[g_csr_dst[k]];
        e = e > 0.f ? e : NEG_SLOPE * e;
        float mn = fmaxf(m, e);
        den = den * __expf(m - mn) + __expf(e - mn);
        m = mn;
    }
#pragma unroll
    for (int o = 16; o > 0; o >>= 1) {
        float m2 = __shfl_xor_sync(0xffffffffu, m, o);
        float d2 = __shfl_xor_sync(0xffffffffu, den, o);
        float mn = fmaxf(m, m2);
        den = den * __expf(m - mn) + d2 * __expf(m2 - mn);
        m = mn;
    }
    float inv = den > 0.f ? 1.0f / den : 0.0f;

    // aggregation: stage 32 edges/chunk in regs, broadcast 4 at a time (MLP=4)
    float2 acc = make_float2(0.f, 0.f);
    for (int base = beg; base < end; base += 32) {
        int k = base + lane;
        int   dk   = 0;
        float attk = 0.f;
        if (k < end) {
            dk = g_csr_dst[k];
            float e = sn + g_d[dk];
            e = e > 0.f ? e : NEG_SLOPE * e;
            attk = __expf(e - m) * inv;
        }
        int cnt = min(32, end - base);
        for (int t = 0; t < cnt; t += 4) {
            int   d0 = __shfl_sync(0xffffffffu, dk, t);
            int   d1 = __shfl_sync(0xffffffffu, dk, t + 1);
            int   d2 = __shfl_sync(0xffffffffu, dk, t + 2);
            int   d3 = __shfl_sync(0xffffffffu, dk, t + 3);
            float a0 = __shfl_sync(0xffffffffu, attk, t);
            float a1 = __shfl_sync(0xffffffffu, attk, t + 1);
            float a2 = __shfl_sync(0xffffffffu, attk, t + 2);
            float a3 = __shfl_sync(0xffffffffu, attk, t + 3);
            float2 h0 = *(const float2*)(g_Hw1 + d0 * HID + lane * 2);
            float2 h1 = *(const float2*)(g_Hw1 + d1 * HID + lane * 2);
            float2 h2 = *(const float2*)(g_Hw1 + d2 * HID + lane * 2);
            float2 h3 = *(const float2*)(g_Hw1 + d3 * HID + lane * 2);
            acc.x = fmaf(a0, h0.x, acc.x); acc.y = fmaf(a0, h0.y, acc.y);
            acc.x = fmaf(a1, h1.x, acc.x); acc.y = fmaf(a1, h1.y, acc.y);
            acc.x = fmaf(a2, h2.x, acc.x); acc.y = fmaf(a2, h2.y, acc.y);
            acc.x = fmaf(a3, h3.x, acc.x); acc.y = fmaf(a3, h3.y, acc.y);
        }
    }
    acc.x = acc.x > 0.f ? acc.x : expm1f(acc.x);
    acc.y = acc.y > 0.f ? acc.y : expm1f(acc.y);
    *(float2*)(g_agg + n * HID + lane * 2) = acc;
}

// layer 2: D=32 (float/lane), epilogue log_softmax -> out
__global__ void k_softagg32(float* __restrict__ out) {
    int n = blockIdx.x * 8 + (threadIdx.x >> 5);
    int lane = threadIdx.x & 31;
    int beg = g_off[n], end = g_off[n + 1];
    float sn = g_s[n];

    float m = -1e30f, den = 0.f;
    for (int k = beg + lane; k < end; k += 32) {
        float e = sn + g_d[g_csr_dst[k]];
        e = e > 0.f ? e : NEG_SLOPE * e;
        float mn = fmaxf(m, e);
        den = den * __expf(m - mn) + __expf(e - mn);
        m = mn;
    }
#pragma unroll
    for (int o = 16; o > 0; o >>= 1) {
        float m2 = __shfl_xor_sync(0xffffffffu, m, o);
        float d2 = __shfl_xor_sync(0xffffffffu, den, o);
        float mn = fmaxf(m, m2);
        den = den * __expf(m - mn) + d2 * __expf(m2 - mn);
        m = mn;
    }
    float inv = den > 0.f ? 1.0f / den : 0.0f;

    float acc = 0.f;
    for (int base = beg; base < end; base += 32) {
        int k = base + lane;
        int   dk   = 0;
        float attk = 0.f;
        if (k < end) {
            dk = g_csr_dst[k];
            float e = sn + g_d[dk];
            e = e > 0.f ? e : NEG_SLOPE * e;
            attk = __expf(e - m) * inv;
        }
        int cnt = min(32, end - base);
        for (int t = 0; t < cnt; t += 4) {
            int   d0 = __shfl_sync(0xffffffffu, dk, t);
            int   d1 = __shfl_sync(0xffffffffu, dk, t + 1);
            int   d2 = __shfl_sync(0xffffffffu, dk, t + 2);
            int   d3 = __shfl_sync(0xffffffffu, dk, t + 3);
            float a0 = __shfl_sync(0xffffffffu, attk, t);
            float a1 = __shfl_sync(0xffffffffu, attk, t + 1);
            float a2 = __shfl_sync(0xffffffffu, attk, t + 2);
            float a3 = __shfl_sync(0xffffffffu, attk, t + 3);
            float h0 = g_Hw2[d0 * CLS + lane];
            float h1 = g_Hw2[d1 * CLS + lane];
            float h2 = g_Hw2[d2 * CLS + lane];
            float h3 = g_Hw2[d3 * CLS + lane];
            acc = fmaf(a0, h0, acc);
            acc = fmaf(a1, h1, acc);
            acc = fmaf(a2, h2, acc);
            acc = fmaf(a3, h3, acc);
        }
    }
    // fused log_softmax over 32 classes (one per lane)
    float mx = acc;
#pragma unroll
    for (int o = 16; o > 0; o >>= 1) mx = fmaxf(mx, __shfl_xor_sync(0xffffffffu, mx, o));
    float ex = __expf(acc - mx);
    float sm = ex;
#pragma unroll
    for (int o = 16; o > 0; o >>= 1) sm += __shfl_xor_sync(0xffffffffu, sm, o);
    out[n * CLS + lane] = acc - mx - __logf(sm);
}

// ================= launch ====================================================
extern "C" void kernel_launch(void* const* d_in, const int* in_sizes, int n_in,
                              void* d_out, int out_size) {
    const float* X  = (const float*)d_in[0];
    const int*   EI = (const int*)d_in[1];     // int32 (JAX x64 disabled)
    const float* W1 = (const float*)d_in[2];
    const float* W2 = (const float*)d_in[3];
    const float* A1 = (const float*)d_in[4];
    const float* A2 = (const float*)d_in[5];
    float* out = (float*)d_out;

    const int T = 256;
    int g_nodes = (N_NODES + T - 1) / T;       // 391
    int g_edges = (N_EDGES + T - 1) / T;       // 6250

    // CSR build (shared by both layers)
    k_zero<<<g_nodes, T>>>();
    k_count<<<g_edges, T>>>(EI);
    k_scan1<<<NBLK_SCAN, 256>>>();
    k_scan2<<<1, 512>>>();
    k_scan3<<<g_nodes, T>>>();
    k_fill<<<g_edges, T>>>(EI);

    // layer 1
    k_gemm1<<<N_NODES / 32, 256>>>(X, W1, A1);
    k_softagg64<<<N_NODES / 8, 256>>>();

    // layer 2
    k_gemm2<<<N_NODES / 4, 128>>>(W2, A2);
    k_softagg32<<<N_NODES / 8, 256>>>(out);
}

// round 6
// speedup vs baseline: 2.2881x; 1.0307x over previous
#include <cuda_runtime.h>
#include <math.h>

#define N_NODES   100000
#define N_EDGES   1600000
#define IN_DIM    256
#define HID       64
#define CLS       32
#define NEG_SLOPE 0.01f
#define NBLK_SCAN ((N_NODES + 255) / 256)   // 391

// ---------------- scratch (device globals; no allocations allowed) ----------
__device__ float g_Hw1[N_NODES * HID];
__device__ float g_agg[N_NODES * HID];
__device__ float g_Hw2[N_NODES * CLS];
__device__ float g_s[N_NODES];
__device__ float g_d[N_NODES];
__device__ int   g_deg[N_NODES];
__device__ int   g_off[N_NODES + 1];
__device__ int   g_pos[N_NODES];
__device__ int   g_csr_dst[N_EDGES];
__device__ int   g_bsum[NBLK_SCAN];
__device__ int   g_bscan[NBLK_SCAN];

// ================= CSR build =================================================
__global__ void k_zero() {
    int i = blockIdx.x * blockDim.x + threadIdx.x;
    if (i < N_NODES) { g_deg[i] = 0; g_pos[i] = 0; }
}

__global__ void k_count(const int* __restrict__ ei) {
    int i = blockIdx.x * blockDim.x + threadIdx.x;
    if (i < N_EDGES) atomicAdd(&g_deg[ei[i]], 1);
}

__global__ void k_scan1() {
    __shared__ int sh[256];
    int t = threadIdx.x;
    int i = blockIdx.x * 256 + t;
    int v = (i < N_NODES) ? g_deg[i] : 0;
    sh[t] = v;
    __syncthreads();
#pragma unroll
    for (int o = 1; o < 256; o <<= 1) {
        int x = (t >= o) ? sh[t - o] : 0;
        __syncthreads();
        sh[t] += x;
        __syncthreads();
    }
    if (i < N_NODES) g_off[i] = sh[t] - v;
    if (t == 255) g_bsum[blockIdx.x] = sh[255];
}

__global__ void k_scan2() {
    __shared__ int sh[512];
    int t = threadIdx.x;
    int v = (t < NBLK_SCAN) ? g_bsum[t] : 0;
    sh[t] = v;
    __syncthreads();
#pragma unroll
    for (int o = 1; o < 512; o <<= 1) {
        int x = (t >= o) ? sh[t - o] : 0;
        __syncthreads();
        sh[t] += x;
        __syncthreads();
    }
    if (t < NBLK_SCAN) g_bscan[t] = sh[t] - v;
}

__global__ void k_scan3() {
    int i = blockIdx.x * blockDim.x + threadIdx.x;
    if (i < N_NODES) g_off[i] += g_bscan[i >> 8];
    if (i == 0) g_off[N_NODES] = N_EDGES;
}

__global__ void k_fill(const int* __restrict__ ei) {
    int i = blockIdx.x * blockDim.x + threadIdx.x;
    if (i >= N_EDGES) return;
    int s = ei[i];
    int slot = g_off[s] + atomicAdd(&g_pos[s], 1);
    g_csr_dst[slot] = ei[N_EDGES + i];
}

// ================= layer-1 GEMM + fused scores ==============================
__global__ void k_gemm1(const float* __restrict__ X,
                        const float* __restrict__ W1,
                        const float* __restrict__ A1) {
    __shared__ float Xs[32 * IN_DIM];
    __shared__ float red[8][8][2];
    int node0 = blockIdx.x * 32;

    for (int idx = threadIdx.x * 4; idx < 32 * IN_DIM; idx += 256 * 4)
        *(float4*)(Xs + idx) = *(const float4*)(X + node0 * IN_DIM + idx);
    __syncthreads();

    int j  = threadIdx.x & 63;
    int rg = threadIdx.x >> 6;

    float acc[8];
#pragma unroll
    for (int r = 0; r < 8; ++r) acc[r] = 0.f;

#pragma unroll 4
    for (int k4 = 0; k4 < IN_DIM / 4; ++k4) {
        int k = k4 * 4;
        float w0 = __ldg(&W1[(k + 0) * HID + j]);
        float w1 = __ldg(&W1[(k + 1) * HID + j]);
        float w2 = __ldg(&W1[(k + 2) * HID + j]);
        float w3 = __ldg(&W1[(k + 3) * HID + j]);
#pragma unroll
        for (int r = 0; r < 8; ++r) {
            float4 x = *(const float4*)(Xs + (rg * 8 + r) * IN_DIM + k);
            acc[r] = fmaf(x.x, w0, acc[r]);
            acc[r] = fmaf(x.y, w1, acc[r]);
            acc[r] = fmaf(x.z, w2, acc[r]);
            acc[r] = fmaf(x.w, w3, acc[r]);
        }
    }

    int nb = node0 + rg * 8;
#pragma unroll
    for (int r = 0; r < 8; ++r) g_Hw1[(nb + r) * HID + j] = acc[r];

    float a_s = __ldg(&A1[j]), a_d = __ldg(&A1[HID + j]);
    int w = threadIdx.x >> 5;
#pragma unroll
    for (int r = 0; r < 8; ++r) {
        float sp = acc[r] * a_s;
        float dp = acc[r] * a_d;
#pragma unroll
        for (int o = 16; o > 0; o >>= 1) {
            sp += __shfl_down_sync(0xffffffffu, sp, o);
            dp += __shfl_down_sync(0xffffffffu, dp, o);
        }
        if ((threadIdx.x & 31) == 0) { red[w][r][0] = sp; red[w][r][1] = dp; }
    }
    __syncthreads();
    if (j == 0) {
#pragma unroll
        for (int r = 0; r < 8; ++r) {
            g_s[nb + r] = red[rg * 2][r][0] + red[rg * 2 + 1][r][0];
            g_d[nb + r] = red[rg * 2][r][1] + red[rg * 2 + 1][r][1];
        }
    }
}

// ================= layer-2 GEMM + fused scores ==============================
__global__ void k_gemm2(const float* __restrict__ W2,
                        const float* __restrict__ A2) {
    __shared__ float Hs[4][HID];
    int warp = threadIdx.x >> 5;
    int lane = threadIdx.x & 31;
    int node = blockIdx.x * 4 + warp;

    Hs[warp][lane]      = g_agg[node * HID + lane];
    Hs[warp][32 + lane] = g_agg[node * HID + 32 + lane];
    __syncwarp();

    float acc = 0.0f;
#pragma unroll
    for (int k = 0; k < HID; ++k)
        acc = fmaf(Hs[warp][k], __ldg(&W2[k * CLS + lane]), acc);
    g_Hw2[node * CLS + lane] = acc;

    float sp = acc * __ldg(&A2[lane]);
    float dp = acc * __ldg(&A2[CLS + lane]);
#pragma unroll
    for (int o = 16; o > 0; o >>= 1) {
        sp += __shfl_down_sync(0xffffffffu, sp, o);
        dp += __shfl_down_sync(0xffffffffu, dp, o);
    }
    if (lane == 0) { g_s[node] = sp; g_d[node] = dp; }
}

// ================= softmax + aggregate (warp/node) ==========================
// First 32 edges live in registers (one per lane): dst + score loaded ONCE.
// deg > 32 handled by an online-softmax tail + extra agg chunks.
// layer 1: D=64 (float2/lane), epilogue ELU -> g_agg
__global__ void k_softagg64() {
    int n = blockIdx.x * 8 + (threadIdx.x >> 5);
    int lane = threadIdx.x & 31;
    int beg = g_off[n], end = g_off[n + 1];
    int deg = end - beg;
    float sn = g_s[n];

    // first chunk in registers
    int dk = 0; float ek = -1e30f;
    if (lane < deg) {
        dk = g_csr_dst[beg + lane];
        float e = sn + g_d[dk];
        ek = e > 0.f ? e : NEG_SLOPE * e;
    }

    // per-lane stats: tail edges (rare) + own first-chunk value
    float mx = -1e30f, den = 0.f;
    if (deg > 32) {
        for (int k = beg + 32 + lane; k < end; k += 32) {
            int d2 = g_csr_dst[k];
            float e = sn + g_d[d2];
            e = e > 0.f ? e : NEG_SLOPE * e;
            float mn = fmaxf(mx, e);
            den = den * __expf(mx - mn) + __expf(e - mn);
            mx = mn;
        }
    }
    {
        float mn = fmaxf(mx, ek);
        den = den * __expf(mx - mn) + ((lane < deg) ? __expf(ek - mn) : 0.f);
        mx = mn;
    }
#pragma unroll
    for (int o = 16; o > 0; o >>= 1) {
        float m2 = __shfl_xor_sync(0xffffffffu, mx, o);
        float d2 = __shfl_xor_sync(0xffffffffu, den, o);
        float mn = fmaxf(mx, m2);
        den = den * __expf(mx - mn) + d2 * __expf(m2 - mn);
        mx = mn;
    }
    float inv = (deg > 0) ? 1.0f / den : 0.0f;
    float attk = (lane < deg) ? __expf(ek - mx) * inv : 0.0f;

    // aggregation, first chunk from registers, MLP=8
    float2 acc = make_float2(0.f, 0.f);
    int cnt = min(deg, 32);
    for (int t = 0; t < cnt; t += 8) {
        int dd[8]; float aa[8]; float2 hh[8];
#pragma unroll
        for (int u = 0; u < 8; ++u) {
            dd[u] = __shfl_sync(0xffffffffu, dk, t + u);
            aa[u] = __shfl_sync(0xffffffffu, attk, t + u);
        }
#pragma unroll
        for (int u = 0; u < 8; ++u)
            hh[u] = *(const float2*)(g_Hw1 + dd[u] * HID + lane * 2);
#pragma unroll
        for (int u = 0; u < 8; ++u) {
            acc.x = fmaf(aa[u], hh[u].x, acc.x);
            acc.y = fmaf(aa[u], hh[u].y, acc.y);
        }
    }
    // tail chunks (deg > 32)
    for (int base = beg + 32; base < end; base += 32) {
        int k = base + lane;
        int dk2 = 0; float att2 = 0.f;
        if (k < end) {
            dk2 = g_csr_dst[k];
            float e = sn + g_d[dk2];
            e = e > 0.f ? e : NEG_SLOPE * e;
            att2 = __expf(e - mx) * inv;
        }
        int cnt2 = min(32, end - base);
        for (int t = 0; t < cnt2; t += 8) {
            int dd[8]; float aa[8]; float2 hh[8];
#pragma unroll
            for (int u = 0; u < 8; ++u) {
                dd[u] = __shfl_sync(0xffffffffu, dk2, t + u);
                aa[u] = __shfl_sync(0xffffffffu, att2, t + u);
            }
#pragma unroll
            for (int u = 0; u < 8; ++u)
                hh[u] = *(const float2*)(g_Hw1 + dd[u] * HID + lane * 2);
#pragma unroll
            for (int u = 0; u < 8; ++u) {
                acc.x = fmaf(aa[u], hh[u].x, acc.x);
                acc.y = fmaf(aa[u], hh[u].y, acc.y);
            }
        }
    }
    acc.x = acc.x > 0.f ? acc.x : expm1f(acc.x);
    acc.y = acc.y > 0.f ? acc.y : expm1f(acc.y);
    *(float2*)(g_agg + n * HID + lane * 2) = acc;
}

// layer 2: D=32 (float/lane), epilogue log_softmax -> out
__global__ void k_softagg32(float* __restrict__ out) {
    int n = blockIdx.x * 8 + (threadIdx.x >> 5);
    int lane = threadIdx.x & 31;
    int beg = g_off[n], end = g_off[n + 1];
    int deg = end - beg;
    float sn = g_s[n];

    int dk = 0; float ek = -1e30f;
    if (lane < deg) {
        dk = g_csr_dst[beg + lane];
        float e = sn + g_d[dk];
        ek = e > 0.f ? e : NEG_SLOPE * e;
    }

    float mx = -1e30f, den = 0.f;
    if (deg > 32) {
        for (int k = beg + 32 + lane; k < end; k += 32) {
            int d2 = g_csr_dst[k];
            float e = sn + g_d[d2];
            e = e > 0.f ? e : NEG_SLOPE * e;
            float mn = fmaxf(mx, e);
            den = den * __expf(mx - mn) + __expf(e - mn);
            mx = mn;
        }
    }
    {
        float mn = fmaxf(mx, ek);
        den = den * __expf(mx - mn) + ((lane < deg) ? __expf(ek - mn) : 0.f);
        mx = mn;
    }
#pragma unroll
    for (int o = 16; o > 0; o >>= 1) {
        float m2 = __shfl_xor_sync(0xffffffffu, mx, o);
        float d2 = __shfl_xor_sync(0xffffffffu, den, o);
        float mn = fmaxf(mx, m2);
        den = den * __expf(mx - mn) + d2 * __expf(m2 - mn);
        mx = mn;
    }
    float inv = (deg > 0) ? 1.0f / den : 0.0f;
    float attk = (lane < deg) ? __expf(ek - mx) * inv : 0.0f;

    float acc = 0.f;
    int cnt = min(deg, 32);
    for (int t = 0; t < cnt; t += 8) {
        int dd[8]; float aa[8]; float hh[8];
#pragma unroll
        for (int u = 0; u < 8; ++u) {
            dd[u] = __shfl_sync(0xffffffffu, dk, t + u);
            aa[u] = __shfl_sync(0xffffffffu, attk, t + u);
        }
#pragma unroll
        for (int u = 0; u < 8; ++u)
            hh[u] = g_Hw2[dd[u] * CLS + lane];
#pragma unroll
        for (int u = 0; u < 8; ++u)
            acc = fmaf(aa[u], hh[u], acc);
    }
    for (int base = beg + 32; base < end; base += 32) {
        int k = base + lane;
        int dk2 = 0; float att2 = 0.f;
        if (k < end) {
            dk2 = g_csr_dst[k];
            float e = sn + g_d[dk2];
            e = e > 0.f ? e : NEG_SLOPE * e;
            att2 = __expf(e - mx) * inv;
        }
        int cnt2 = min(32, end - base);
        for (int t = 0; t < cnt2; t += 8) {
            int dd[8]; float aa[8]; float hh[8];
#pragma unroll
            for (int u = 0; u < 8; ++u) {
                dd[u] = __shfl_sync(0xffffffffu, dk2, t + u);
                aa[u] = __shfl_sync(0xffffffffu, att2, t + u);
            }
#pragma unroll
            for (int u = 0; u < 8; ++u)
                hh[u] = g_Hw2[dd[u] * CLS + lane];
#pragma unroll
            for (int u = 0; u < 8; ++u)
                acc = fmaf(aa[u], hh[u], acc);
        }
    }
    // fused log_softmax
    float m2 = acc;
#pragma unroll
    for (int o = 16; o > 0; o >>= 1) m2 = fmaxf(m2, __shfl_xor_sync(0xffffffffu, m2, o));
    float ex = __expf(acc - m2);
    float sm = ex;
#pragma unroll
    for (int o = 16; o > 0; o >>= 1) sm += __shfl_xor_sync(0xffffffffu, sm, o);
    out[n * CLS + lane] = acc - m2 - __logf(sm);
}

// ================= launch ====================================================
extern "C" void kernel_launch(void* const* d_in, const int* in_sizes, int n_in,
                              void* d_out, int out_size) {
    const float* X  = (const float*)d_in[0];
    const int*   EI = (const int*)d_in[1];
    const float* W1 = (const float*)d_in[2];
    const float* W2 = (const float*)d_in[3];
    const float* A1 = (const float*)d_in[4];
    const float* A2 = (const float*)d_in[5];
    float* out = (float*)d_out;

    const int T = 256;
    int g_nodes = (N_NODES + T - 1) / T;
    int g_edges = (N_EDGES + T - 1) / T;

    // CSR build (shared by both layers)
    k_zero<<<g_nodes, T>>>();
    k_count<<<g_edges, T>>>(EI);
    k_scan1<<<NBLK_SCAN, 256>>>();
    k_scan2<<<1, 512>>>();
    k_scan3<<<g_nodes, T>>>();
    k_fill<<<g_edges, T>>>(EI);

    // layer 1
    k_gemm1<<<N_NODES / 32, 256>>>(X, W1, A1);
    k_softagg64<<<N_NODES / 8, 256>>>();

    // layer 2
    k_gemm2<<<N_NODES / 4, 128>>>(W2, A2);
    k_softagg32<<<N_NODES / 8, 256>>>(out);
}

// round 7
// speedup vs baseline: 2.9992x; 1.3108x over previous
#include <cuda_runtime.h>
#include <cuda_bf16.h>
#include <math.h>
#include <stdint.h>

#define N_NODES   100000
#define N_EDGES   1600000
#define IN_DIM    256
#define HID       64
#define CLS       32
#define NEG_SLOPE 0.01f
#define NBLK_SCAN ((N_NODES + 255) / 256)   // 391

#define BM      128                 // nodes per gemm1 block
#define KCHUNK  128                 // K columns staged per chunk
#define KPAD    136                 // padded bf16 row stride (conflict-free)
#define GEMM1_SMEM (2 * BM * KPAD * 2)      // hi+lo bf16 stage = 69632 B

// ---------------- scratch (device globals; no allocations allowed) ----------
__device__ float    g_Hw1[N_NODES * HID];
__device__ float    g_agg[N_NODES * HID];
__device__ float    g_Hw2[N_NODES * CLS];
__device__ float    g_s[N_NODES];
__device__ float    g_d[N_NODES];
__device__ int      g_deg[N_NODES];
__device__ int      g_off[N_NODES + 1];
__device__ int      g_pos[N_NODES];
__device__ int      g_csr_dst[N_EDGES];
__device__ int      g_bsum[NBLK_SCAN];
__device__ int      g_bscan[NBLK_SCAN];
__device__ uint32_t g_Wpack[2 * 16 * 8 * 32 * 2];   // [hi/lo][kstep][nb][lane][reg]

// ================= CSR build =================================================
__global__ void k_zero() {
    int i = blockIdx.x * blockDim.x + threadIdx.x;
    if (i < N_NODES) { g_deg[i] = 0; g_pos[i] = 0; }
}

__global__ void k_count(const int* __restrict__ ei) {
    int i = blockIdx.x * blockDim.x + threadIdx.x;
    if (i < N_EDGES) atomicAdd(&g_deg[ei[i]], 1);
}

__global__ void k_scan1() {
    __shared__ int sh[256];
    int t = threadIdx.x;
    int i = blockIdx.x * 256 + t;
    int v = (i < N_NODES) ? g_deg[i] : 0;
    sh[t] = v;
    __syncthreads();
#pragma unroll
    for (int o = 1; o < 256; o <<= 1) {
        int x = (t >= o) ? sh[t - o] : 0;
        __syncthreads();
        sh[t] += x;
        __syncthreads();
    }
    if (i < N_NODES) g_off[i] = sh[t] - v;
    if (t == 255) g_bsum[blockIdx.x] = sh[255];
}

__global__ void k_scan2() {
    __shared__ int sh[512];
    int t = threadIdx.x;
    int v = (t < NBLK_SCAN) ? g_bsum[t] : 0;
    sh[t] = v;
    __syncthreads();
#pragma unroll
    for (int o = 1; o < 512; o <<= 1) {
        int x = (t >= o) ? sh[t - o] : 0;
        __syncthreads();
        sh[t] += x;
        __syncthreads();
    }
    if (t < NBLK_SCAN) g_bscan[t] = sh[t] - v;
}

__global__ void k_scan3() {
    int i = blockIdx.x * blockDim.x + threadIdx.x;
    if (i < N_NODES) g_off[i] += g_bscan[i >> 8];
    if (i == 0) g_off[N_NODES] = N_EDGES;
}

__global__ void k_fill(const int* __restrict__ ei) {
    int i = blockIdx.x * blockDim.x + threadIdx.x;
    if (i >= N_EDGES) return;
    int s = ei[i];
    int slot = g_off[s] + atomicAdd(&g_pos[s], 1);
    g_csr_dst[slot] = ei[N_EDGES + i];
}

// ================= W1 pack (bf16 hi/lo, mma B-fragment order) ================
// thread = (kstep, nb, lane); B frag: reg r = {W[k0+(lane%4)*2+8r][n], W[k0+(lane%4)*2+1+8r][n]}
__global__ void k_packW(const float* __restrict__ W1) {
    int idx = blockIdx.x * blockDim.x + threadIdx.x;   // 0..4095
    int ks   = idx >> 8;          // 0..15
    int nb   = (idx >> 5) & 7;    // 0..7
    int lane = idx & 31;
    int n  = nb * 8 + (lane >> 2);
    int k0 = ks * 16 + (lane & 3) * 2;
#pragma unroll
    for (int r = 0; r < 2; ++r) {
        int k = k0 + r * 8;
        float w0 = W1[k * HID + n];
        float w1 = W1[(k + 1) * HID + n];
        __nv_bfloat162 h = __float22bfloat162_rn(make_float2(w0, w1));
        float l0f = w0 - __low2float(h);
        float l1f = w1 - __high2float(h);
        __nv_bfloat162 l = __float22bfloat162_rn(make_float2(l0f, l1f));
        g_Wpack[((0 * 16 + ks) * 8 + nb) * 64 + lane * 2 + r] = *(uint32_t*)&h;
        g_Wpack[((1 * 16 + ks) * 8 + nb) * 64 + lane * 2 + r] = *(uint32_t*)&l;
    }
}

// ================= layer-1 GEMM: tensor cores, bf16 split ===================
__device__ __forceinline__ void mma16816(float* c, uint32_t a0, uint32_t a1,
                                         uint32_t a2, uint32_t a3,
                                         uint32_t b0, uint32_t b1) {
    asm volatile(
        "mma.sync.aligned.m16n8k16.row.col.f32.bf16.bf16.f32 "
        "{%0,%1,%2,%3}, {%4,%5,%6,%7}, {%8,%9}, {%0,%1,%2,%3};\n"
        : "+f"(c[0]), "+f"(c[1]), "+f"(c[2]), "+f"(c[3])
        : "r"(a0), "r"(a1), "r"(a2), "r"(a3), "r"(b0), "r"(b1));
}

__global__ __launch_bounds__(256) void k_gemm1_mma(const float* __restrict__ X) {
    extern __shared__ unsigned short sm[];
    unsigned short* Ahi = sm;                    // [BM][KPAD] bf16
    unsigned short* Alo = sm + BM * KPAD;

    int tid  = threadIdx.x;
    int warp = tid >> 5;
    int lane = tid & 31;
    int row0 = blockIdx.x * BM;

    float acc[8][4];
#pragma unroll
    for (int nb = 0; nb < 8; ++nb)
#pragma unroll
        for (int r = 0; r < 4; ++r) acc[nb][r] = 0.f;

    for (int chunk = 0; chunk < IN_DIM / KCHUNK; ++chunk) {
        __syncthreads();
        // stage 128x128 fp32 -> bf16 hi/lo smem
        for (int i = tid; i < BM * (KCHUNK / 4); i += 256) {
            int r  = i >> 5;             // row 0..127
            int c4 = i & 31;             // float4 index within chunk
            float4 v = make_float4(0.f, 0.f, 0.f, 0.f);
            if (row0 + r < N_NODES)
                v = __ldg((const float4*)(X + (size_t)(row0 + r) * IN_DIM
                                            + chunk * KCHUNK + c4 * 4));
            __nv_bfloat162 h01 = __float22bfloat162_rn(make_float2(v.x, v.y));
            __nv_bfloat162 h23 = __float22bfloat162_rn(make_float2(v.z, v.w));
            __nv_bfloat162 l01 = __float22bfloat162_rn(
                make_float2(v.x - __low2float(h01), v.y - __high2float(h01)));
            __nv_bfloat162 l23 = __float22bfloat162_rn(
                make_float2(v.z - __low2float(h23), v.w - __high2float(h23)));
            uint32_t base = r * KPAD + c4 * 4;
            *(uint32_t*)(Ahi + base)     = *(uint32_t*)&h01;
            *(uint32_t*)(Ahi + base + 2) = *(uint32_t*)&h23;
            *(uint32_t*)(Alo + base)     = *(uint32_t*)&l01;
            *(uint32_t*)(Alo + base + 2) = *(uint32_t*)&l23;
        }
        __syncthreads();

        int rA = warp * 16 + (lane >> 2);
#pragma unroll
        for (int ks = 0; ks < KCHUNK / 16; ++ks) {
            int kc = ks * 16 + (lane & 3) * 2;
            uint32_t ah0 = *(uint32_t*)(Ahi + rA * KPAD + kc);
            uint32_t ah1 = *(uint32_t*)(Ahi + (rA + 8) * KPAD + kc);
            uint32_t ah2 = *(uint32_t*)(Ahi + rA * KPAD + kc + 8);
            uint32_t ah3 = *(uint32_t*)(Ahi + (rA + 8) * KPAD + kc + 8);
            uint32_t al0 = *(uint32_t*)(Alo + rA * KPAD + kc);
            uint32_t al1 = *(uint32_t*)(Alo + (rA + 8) * KPAD + kc);
            uint32_t al2 = *(uint32_t*)(Alo + rA * KPAD + kc + 8);
            uint32_t al3 = *(uint32_t*)(Alo + (rA + 8) * KPAD + kc + 8);
            int ksg = chunk * (KCHUNK / 16) + ks;
#pragma unroll
            for (int nb = 0; nb < 8; ++nb) {
                uint2 bh = __ldg((const uint2*)(g_Wpack + ((0 * 16 + ksg) * 8 + nb) * 64 + lane * 2));
                uint2 bl = __ldg((const uint2*)(g_Wpack + ((1 * 16 + ksg) * 8 + nb) * 64 + lane * 2));
                mma16816(acc[nb], ah0, ah1, ah2, ah3, bh.x, bh.y);
                mma16816(acc[nb], ah0, ah1, ah2, ah3, bl.x, bl.y);
                mma16816(acc[nb], al0, al1, al2, al3, bh.x, bh.y);
            }
        }
    }

    // epilogue: C[r][c]: c0,c1 at (row, col..col+1), c2,c3 at (row+8, ...)
    int rowA = row0 + warp * 16 + (lane >> 2);
    int colA = (lane & 3) * 2;
#pragma unroll
    for (int nb = 0; nb < 8; ++nb) {
        int col = nb * 8 + colA;
        if (rowA < N_NODES)
            *(float2*)(g_Hw1 + (size_t)rowA * HID + col) = make_float2(acc[nb][0], acc[nb][1]);
        if (rowA + 8 < N_NODES)
            *(float2*)(g_Hw1 + (size_t)(rowA + 8) * HID + col) = make_float2(acc[nb][2], acc[nb][3]);
    }
}

// ================= layer-1 attention scores ==================================
__global__ void k_score1(const float* __restrict__ A1) {
    int node = blockIdx.x * 8 + (threadIdx.x >> 5);   // 12500*8 = 100000 exact
    int lane = threadIdx.x & 31;
    float2 h = *(const float2*)(g_Hw1 + (size_t)node * HID + lane * 2);
    int j = lane * 2;
    float sp = h.x * __ldg(&A1[j])       + h.y * __ldg(&A1[j + 1]);
    float dp = h.x * __ldg(&A1[HID + j]) + h.y * __ldg(&A1[HID + j + 1]);
#pragma unroll
    for (int o = 16; o > 0; o >>= 1) {
        sp += __shfl_down_sync(0xffffffffu, sp, o);
        dp += __shfl_down_sync(0xffffffffu, dp, o);
    }
    if (lane == 0) { g_s[node] = sp; g_d[node] = dp; }
}

// ================= layer-2 GEMM + fused scores ==============================
__global__ void k_gemm2(const float* __restrict__ W2,
                        const float* __restrict__ A2) {
    __shared__ float Hs[4][HID];
    int warp = threadIdx.x >> 5;
    int lane = threadIdx.x & 31;
    int node = blockIdx.x * 4 + warp;

    Hs[warp][lane]      = g_agg[node * HID + lane];
    Hs[warp][32 + lane] = g_agg[node * HID + 32 + lane];
    __syncwarp();

    float acc = 0.0f;
#pragma unroll
    for (int k = 0; k < HID; ++k)
        acc = fmaf(Hs[warp][k], __ldg(&W2[k * CLS + lane]), acc);
    g_Hw2[node * CLS + lane] = acc;

    float sp = acc * __ldg(&A2[lane]);
    float dp = acc * __ldg(&A2[CLS + lane]);
#pragma unroll
    for (int o = 16; o > 0; o >>= 1) {
        sp += __shfl_down_sync(0xffffffffu, sp, o);
        dp += __shfl_down_sync(0xffffffffu, dp, o);
    }
    if (lane == 0) { g_s[node] = sp; g_d[node] = dp; }
}

// ================= softmax + aggregate (warp/node) ==========================
__global__ void k_softagg64() {
    int n = blockIdx.x * 8 + (threadIdx.x >> 5);
    int lane = threadIdx.x & 31;
    int beg = g_off[n], end = g_off[n + 1];
    int deg = end - beg;
    float sn = g_s[n];

    int dk = 0; float ek = -1e30f;
    if (lane < deg) {
        dk = g_csr_dst[beg + lane];
        float e = sn + g_d[dk];
        ek = e > 0.f ? e : NEG_SLOPE * e;
    }

    float mx = -1e30f, den = 0.f;
    if (deg > 32) {
        for (int k = beg + 32 + lane; k < end; k += 32) {
            int d2 = g_csr_dst[k];
            float e = sn + g_d[d2];
            e = e > 0.f ? e : NEG_SLOPE * e;
            float mn = fmaxf(mx, e);
            den = den * __expf(mx - mn) + __expf(e - mn);
            mx = mn;
        }
    }
    {
        float mn = fmaxf(mx, ek);
        den = den * __expf(mx - mn) + ((lane < deg) ? __expf(ek - mn) : 0.f);
        mx = mn;
    }
#pragma unroll
    for (int o = 16; o > 0; o >>= 1) {
        float m2 = __shfl_xor_sync(0xffffffffu, mx, o);
        float d2 = __shfl_xor_sync(0xffffffffu, den, o);
        float mn = fmaxf(mx, m2);
        den = den * __expf(mx - mn) + d2 * __expf(m2 - mn);
        mx = mn;
    }
    float inv = (deg > 0) ? 1.0f / den : 0.0f;
    float attk = (lane < deg) ? __expf(ek - mx) * inv : 0.0f;

    float2 acc = make_float2(0.f, 0.f);
    int cnt = min(deg, 32);
    for (int t = 0; t < cnt; t += 8) {
        int dd[8]; float aa[8]; float2 hh[8];
#pragma unroll
        for (int u = 0; u < 8; ++u) {
            dd[u] = __shfl_sync(0xffffffffu, dk, t + u);
            aa[u] = __shfl_sync(0xffffffffu, attk, t + u);
        }
#pragma unroll
        for (int u = 0; u < 8; ++u)
            hh[u] = *(const float2*)(g_Hw1 + dd[u] * HID + lane * 2);
#pragma unroll
        for (int u = 0; u < 8; ++u) {
            acc.x = fmaf(aa[u], hh[u].x, acc.x);
            acc.y = fmaf(aa[u], hh[u].y, acc.y);
        }
    }
    for (int base = beg + 32; base < end; base += 32) {
        int k = base + lane;
        int dk2 = 0; float att2 = 0.f;
        if (k < end) {
            dk2 = g_csr_dst[k];
            float e = sn + g_d[dk2];
            e = e > 0.f ? e : NEG_SLOPE * e;
            att2 = __expf(e - mx) * inv;
        }
        int cnt2 = min(32, end - base);
        for (int t = 0; t < cnt2; t += 8) {
            int dd[8]; float aa[8]; float2 hh[8];
#pragma unroll
            for (int u = 0; u < 8; ++u) {
                dd[u] = __shfl_sync(0xffffffffu, dk2, t + u);
                aa[u] = __shfl_sync(0xffffffffu, att2, t + u);
            }
#pragma unroll
            for (int u = 0; u < 8; ++u)
                hh[u] = *(const float2*)(g_Hw1 + dd[u] * HID + lane * 2);
#pragma unroll
            for (int u = 0; u < 8; ++u) {
                acc.x = fmaf(aa[u], hh[u].x, acc.x);
                acc.y = fmaf(aa[u], hh[u].y, acc.y);
            }
        }
    }
    acc.x = acc.x > 0.f ? acc.x : expm1f(acc.x);
    acc.y = acc.y > 0.f ? acc.y : expm1f(acc.y);
    *(float2*)(g_agg + n * HID + lane * 2) = acc;
}

__global__ void k_softagg32(float* __restrict__ out) {
    int n = blockIdx.x * 8 + (threadIdx.x >> 5);
    int lane = threadIdx.x & 31;
    int beg = g_off[n], end = g_off[n + 1];
    int deg = end - beg;
    float sn = g_s[n];

    int dk = 0; float ek = -1e30f;
    if (lane < deg) {
        dk = g_csr_dst[beg + lane];
        float e = sn + g_d[dk];
        ek = e > 0.f ? e : NEG_SLOPE * e;
    }

    float mx = -1e30f, den = 0.f;
    if (deg > 32) {
        for (int k = beg + 32 + lane; k < end; k += 32) {
            int d2 = g_csr_dst[k];
            float e = sn + g_d[d2];
            e = e > 0.f ? e : NEG_SLOPE * e;
            float mn = fmaxf(mx, e);
            den = den * __expf(mx - mn) + __expf(e - mn);
            mx = mn;
        }
    }
    {
        float mn = fmaxf(mx, ek);
        den = den * __expf(mx - mn) + ((lane < deg) ? __expf(ek - mn) : 0.f);
        mx = mn;
    }
#pragma unroll
    for (int o = 16; o > 0; o >>= 1) {
        float m2 = __shfl_xor_sync(0xffffffffu, mx, o);
        float d2 = __shfl_xor_sync(0xffffffffu, den, o);
        float mn = fmaxf(mx, m2);
        den = den * __expf(mx - mn) + d2 * __expf(m2 - mn);
        mx = mn;
    }
    float inv = (deg > 0) ? 1.0f / den : 0.0f;
    float attk = (lane < deg) ? __expf(ek - mx) * inv : 0.0f;

    float acc = 0.f;
    int cnt = min(deg, 32);
    for (int t = 0; t < cnt; t += 8) {
        int dd[8]; float aa[8]; float hh[8];
#pragma unroll
        for (int u = 0; u < 8; ++u) {
            dd[u] = __shfl_sync(0xffffffffu, dk, t + u);
            aa[u] = __shfl_sync(0xffffffffu, attk, t + u);
        }
#pragma unroll
        for (int u = 0; u < 8; ++u)
            hh[u] = g_Hw2[dd[u] * CLS + lane];
#pragma unroll
        for (int u = 0; u < 8; ++u)
            acc = fmaf(aa[u], hh[u], acc);
    }
    for (int base = beg + 32; base < end; base += 32) {
        int k = base + lane;
        int dk2 = 0; float att2 = 0.f;
        if (k < end) {
            dk2 = g_csr_dst[k];
            float e = sn + g_d[dk2];
            e = e > 0.f ? e : NEG_SLOPE * e;
            att2 = __expf(e - mx) * inv;
        }
        int cnt2 = min(32, end - base);
        for (int t = 0; t < cnt2; t += 8) {
            int dd[8]; float aa[8]; float hh[8];
#pragma unroll
            for (int u = 0; u < 8; ++u) {
                dd[u] = __shfl_sync(0xffffffffu, dk2, t + u);
                aa[u] = __shfl_sync(0xffffffffu, att2, t + u);
            }
#pragma unroll
            for (int u = 0; u < 8; ++u)
                hh[u] = g_Hw2[dd[u] * CLS + lane];
#pragma unroll
            for (int u = 0; u < 8; ++u)
                acc = fmaf(aa[u], hh[u], acc);
        }
    }
    float m2 = acc;
#pragma unroll
    for (int o = 16; o > 0; o >>= 1) m2 = fmaxf(m2, __shfl_xor_sync(0xffffffffu, m2, o));
    float ex = __expf(acc - m2);
    float sm = ex;
#pragma unroll
    for (int o = 16; o > 0; o >>= 1) sm += __shfl_xor_sync(0xffffffffu, sm, o);
    out[n * CLS + lane] = acc - m2 - __logf(sm);
}

// ================= launch ====================================================
extern "C" void kernel_launch(void* const* d_in, const int* in_sizes, int n_in,
                              void* d_out, int out_size) {
    const float* X  = (const float*)d_in[0];
    const int*   EI = (const int*)d_in[1];
    const float* W1 = (const float*)d_in[2];
    const float* W2 = (const float*)d_in[3];
    const float* A1 = (const float*)d_in[4];
    const float* A2 = (const float*)d_in[5];
    float* out = (float*)d_out;

    cudaFuncSetAttribute(k_gemm1_mma,
                         cudaFuncAttributeMaxDynamicSharedMemorySize, GEMM1_SMEM);

    const int T = 256;
    int g_nodes = (N_NODES + T - 1) / T;
    int g_edges = (N_EDGES + T - 1) / T;

    // W pack + CSR build
    k_packW<<<16, 256>>>(W1);
    k_zero<<<g_nodes, T>>>();
    k_count<<<g_edges, T>>>(EI);
    k_scan1<<<NBLK_SCAN, 256>>>();
    k_scan2<<<1, 512>>>();
    k_scan3<<<g_nodes, T>>>();
    k_fill<<<g_edges, T>>>(EI);

    // layer 1
    k_gemm1_mma<<<(N_NODES + BM - 1) / BM, 256, GEMM1_SMEM>>>(X);
    k_score1<<<N_NODES / 8, 256>>>(A1);
    k_softagg64<<<N_NODES / 8, 256>>>();

    // layer 2
    k_gemm2<<<N_NODES / 4, 128>>>(W2, A2);
    k_softagg32<<<N_NODES / 8, 256>>>(out);
}

// round 9
// speedup vs baseline: 3.0549x; 1.0186x over previous
#include <cuda_runtime.h>
#include <cuda_bf16.h>
#include <math.h>
#include <stdint.h>

#define N_NODES   100000
#define N_EDGES   1600000
#define IN_DIM    256
#define HID       64
#define CLS       32
#define NEG_SLOPE 0.01f
#define NBLK_SCAN ((N_NODES + 255) / 256)   // 391

#define BM      128
#define KCHUNK  128
#define KPAD    136
#define GEMM1_SMEM (2 * BM * KPAD * 2)      // 69632 B

// ---------------- scratch (device globals; no allocations allowed) ----------
__device__ float    g_Hw1[N_NODES * HID];
__device__ float    g_Hw2[N_NODES * CLS];
__device__ float    g_s[N_NODES];            // layer-1 scores
__device__ float    g_d[N_NODES];
__device__ float    g_s2[N_NODES];           // layer-2 scores (separate: no WAR race)
__device__ float    g_d2[N_NODES];
__device__ int      g_deg[N_NODES];
__device__ int      g_off[N_NODES];          // within-block exclusive scan
__device__ int      g_pos[N_NODES];
__device__ int      g_csr_dst[N_EDGES];
__device__ int      g_bsum[NBLK_SCAN];
__device__ int      g_bscan[NBLK_SCAN];
__device__ uint32_t g_Wpack[2 * 16 * 8 * 32 * 2];

__device__ __forceinline__ int seg_beg(int n) {
    return g_off[n] + g_bscan[n >> 8];
}
__device__ __forceinline__ int seg_end(int n) {
    return (n + 1 < N_NODES) ? (g_off[n + 1] + g_bscan[(n + 1) >> 8]) : N_EDGES;
}

// ================= init: zero counters + pack W1 (bf16 hi/lo B-frags) ========
__global__ void k_init_pack(const float* __restrict__ W1) {
    int idx = blockIdx.x * blockDim.x + threadIdx.x;
    if (idx < N_NODES) { g_deg[idx] = 0; g_pos[idx] = 0; }
    if (idx < 4096) {
        int ks   = idx >> 8;
        int nb   = (idx >> 5) & 7;
        int lane = idx & 31;
        int n  = nb * 8 + (lane >> 2);
        int k0 = ks * 16 + (lane & 3) * 2;
#pragma unroll
        for (int r = 0; r < 2; ++r) {
            int k = k0 + r * 8;
            float w0 = W1[k * HID + n];
            float w1 = W1[(k + 1) * HID + n];
            __nv_bfloat162 h = __float22bfloat162_rn(make_float2(w0, w1));
            __nv_bfloat162 l = __float22bfloat162_rn(
                make_float2(w0 - __low2float(h), w1 - __high2float(h)));
            g_Wpack[((0 * 16 + ks) * 8 + nb) * 64 + lane * 2 + r] = *(uint32_t*)&h;
            g_Wpack[((1 * 16 + ks) * 8 + nb) * 64 + lane * 2 + r] = *(uint32_t*)&l;
        }
    }
}

// ================= CSR build =================================================
__global__ void k_count(const int* __restrict__ ei) {
    int i = blockIdx.x * blockDim.x + threadIdx.x;
    if (i < N_EDGES) atomicAdd(&g_deg[ei[i]], 1);
}

__global__ void k_scan1() {
    __shared__ int sh[256];
    int t = threadIdx.x;
    int i = blockIdx.x * 256 + t;
    int v = (i < N_NODES) ? g_deg[i] : 0;
    sh[t] = v;
    __syncthreads();
#pragma unroll
    for (int o = 1; o < 256; o <<= 1) {
        int x = (t >= o) ? sh[t - o] : 0;
        __syncthreads();
        sh[t] += x;
        __syncthreads();
    }
    if (i < N_NODES) g_off[i] = sh[t] - v;
    if (t == 255) g_bsum[blockIdx.x] = sh[255];
}

__global__ void k_scan2() {
    __shared__ int sh[512];
    int t = threadIdx.x;
    int v = (t < NBLK_SCAN) ? g_bsum[t] : 0;
    sh[t] = v;
    __syncthreads();
#pragma unroll
    for (int o = 1; o < 512; o <<= 1) {
        int x = (t >= o) ? sh[t - o] : 0;
        __syncthreads();
        sh[t] += x;
        __syncthreads();
    }
    if (t < NBLK_SCAN) g_bscan[t] = sh[t] - v;
}

__global__ void k_fill(const int* __restrict__ ei) {
    int i = blockIdx.x * blockDim.x + threadIdx.x;
    if (i >= N_EDGES) return;
    int s = ei[i];
    int slot = seg_beg(s) + atomicAdd(&g_pos[s], 1);
    g_csr_dst[slot] = ei[N_EDGES + i];
}

// ================= layer-1 GEMM (tensor cores, bf16 split) + scores ==========
__device__ __forceinline__ void mma16816(float* c, uint32_t a0, uint32_t a1,
                                         uint32_t a2, uint32_t a3,
                                         uint32_t b0, uint32_t b1) {
    asm volatile(
        "mma.sync.aligned.m16n8k16.row.col.f32.bf16.bf16.f32 "
        "{%0,%1,%2,%3}, {%4,%5,%6,%7}, {%8,%9}, {%0,%1,%2,%3};\n"
        : "+f"(c[0]), "+f"(c[1]), "+f"(c[2]), "+f"(c[3])
        : "r"(a0), "r"(a1), "r"(a2), "r"(a3), "r"(b0), "r"(b1));
}

__global__ __launch_bounds__(256) void k_gemm1_mma(const float* __restrict__ X,
                                                   const float* __restrict__ A1) {
    extern __shared__ unsigned short sm[];
    unsigned short* Ahi = sm;
    unsigned short* Alo = sm + BM * KPAD;

    int tid  = threadIdx.x;
    int warp = tid >> 5;
    int lane = tid & 31;
    int row0 = blockIdx.x * BM;

    float acc[8][4];
#pragma unroll
    for (int nb = 0; nb < 8; ++nb)
#pragma unroll
        for (int r = 0; r < 4; ++r) acc[nb][r] = 0.f;

    for (int chunk = 0; chunk < IN_DIM / KCHUNK; ++chunk) {
        __syncthreads();
        for (int i = tid; i < BM * (KCHUNK / 4); i += 256) {
            int r  = i >> 5;
            int c4 = i & 31;
            float4 v = make_float4(0.f, 0.f, 0.f, 0.f);
            if (row0 + r < N_NODES)
                v = __ldg((const float4*)(X + (size_t)(row0 + r) * IN_DIM
                                            + chunk * KCHUNK + c4 * 4));
            __nv_bfloat162 h01 = __float22bfloat162_rn(make_float2(v.x, v.y));
            __nv_bfloat162 h23 = __float22bfloat162_rn(make_float2(v.z, v.w));
            __nv_bfloat162 l01 = __float22bfloat162_rn(
                make_float2(v.x - __low2float(h01), v.y - __high2float(h01)));
            __nv_bfloat162 l23 = __float22bfloat162_rn(
                make_float2(v.z - __low2float(h23), v.w - __high2float(h23)));
            uint32_t base = r * KPAD + c4 * 4;
            *(uint32_t*)(Ahi + base)     = *(uint32_t*)&h01;
            *(uint32_t*)(Ahi + base + 2) = *(uint32_t*)&h23;
            *(uint32_t*)(Alo + base)     = *(uint32_t*)&l01;
            *(uint32_t*)(Alo + base + 2) = *(uint32_t*)&l23;
        }
        __syncthreads();

        int rA = warp * 16 + (lane >> 2);
#pragma unroll
        for (int ks = 0; ks < KCHUNK / 16; ++ks) {
            int kc = ks * 16 + (lane & 3) * 2;
            uint32_t ah0 = *(uint32_t*)(Ahi + rA * KPAD + kc);
            uint32_t ah1 = *(uint32_t*)(Ahi + (rA + 8) * KPAD + kc);
            uint32_t ah2 = *(uint32_t*)(Ahi + rA * KPAD + kc + 8);
            uint32_t ah3 = *(uint32_t*)(Ahi + (rA + 8) * KPAD + kc + 8);
            uint32_t al0 = *(uint32_t*)(Alo + rA * KPAD + kc);
            uint32_t al1 = *(uint32_t*)(Alo + (rA + 8) * KPAD + kc);
            uint32_t al2 = *(uint32_t*)(Alo + rA * KPAD + kc + 8);
            uint32_t al3 = *(uint32_t*)(Alo + (rA + 8) * KPAD + kc + 8);
            int ksg = chunk * (KCHUNK / 16) + ks;
#pragma unroll
            for (int nb = 0; nb < 8; ++nb) {
                uint2 bh = __ldg((const uint2*)(g_Wpack + ((0 * 16 + ksg) * 8 + nb) * 64 + lane * 2));
                uint2 bl = __ldg((const uint2*)(g_Wpack + ((1 * 16 + ksg) * 8 + nb) * 64 + lane * 2));
                mma16816(acc[nb], ah0, ah1, ah2, ah3, bh.x, bh.y);
                mma16816(acc[nb], ah0, ah1, ah2, ah3, bl.x, bl.y);
                mma16816(acc[nb], al0, al1, al2, al3, bh.x, bh.y);
            }
        }
    }

    int rowA = row0 + warp * 16 + (lane >> 2);
    int colA = (lane & 3) * 2;
#pragma unroll
    for (int nb = 0; nb < 8; ++nb) {
        int col = nb * 8 + colA;
        if (rowA < N_NODES)
            *(float2*)(g_Hw1 + (size_t)rowA * HID + col) = make_float2(acc[nb][0], acc[nb][1]);
        if (rowA + 8 < N_NODES)
            *(float2*)(g_Hw1 + (size_t)(rowA + 8) * HID + col) = make_float2(acc[nb][2], acc[nb][3]);
    }

    // fused attention scores: each 4-lane group holds complete rows rowA, rowA+8
    float s0 = 0.f, d0 = 0.f, s1 = 0.f, d1 = 0.f;
#pragma unroll
    for (int nb = 0; nb < 8; ++nb) {
        int col = nb * 8 + colA;
        float a0 = __ldg(&A1[col]),       a1 = __ldg(&A1[col + 1]);
        float b0 = __ldg(&A1[HID + col]), b1 = __ldg(&A1[HID + col + 1]);
        s0 += acc[nb][0] * a0 + acc[nb][1] * a1;
        d0 += acc[nb][0] * b0 + acc[nb][1] * b1;
        s1 += acc[nb][2] * a0 + acc[nb][3] * a1;
        d1 += acc[nb][2] * b0 + acc[nb][3] * b1;
    }
#pragma unroll
    for (int o = 1; o <= 2; o <<= 1) {
        s0 += __shfl_xor_sync(0xffffffffu, s0, o);
        d0 += __shfl_xor_sync(0xffffffffu, d0, o);
        s1 += __shfl_xor_sync(0xffffffffu, s1, o);
        d1 += __shfl_xor_sync(0xffffffffu, d1, o);
    }
    if ((lane & 3) == 0) {
        if (rowA < N_NODES)     { g_s[rowA] = s0;     g_d[rowA] = d0; }
        if (rowA + 8 < N_NODES) { g_s[rowA + 8] = s1; g_d[rowA + 8] = d1; }
    }
}

// ================= layer-1 softagg + ELU + fused gemm2 + scores ==============
// Reads layer-1 g_s/g_d; writes layer-2 scores to g_s2/g_d2 (no WAR race).
__global__ void k_softagg64g2(const float* __restrict__ W2,
                              const float* __restrict__ A2) {
    __shared__ float W2s[HID * CLS];     // 8 KB
    __shared__ float A2s[2 * CLS];
    for (int i = threadIdx.x; i < HID * CLS; i += 256) W2s[i] = W2[i];
    if (threadIdx.x < 2 * CLS) A2s[threadIdx.x] = A2[threadIdx.x];
    __syncthreads();

    int n = blockIdx.x * 8 + (threadIdx.x >> 5);
    int lane = threadIdx.x & 31;
    int beg = seg_beg(n), end = seg_end(n);
    int deg = end - beg;
    float sn = g_s[n];

    // first 32 edges in registers
    int dk = 0; float ek = -1e30f;
    if (lane < deg) {
        dk = g_csr_dst[beg + lane];
        float e = sn + g_d[dk];
        ek = e > 0.f ? e : NEG_SLOPE * e;
    }

    float mx = -1e30f, den = 0.f;
    if (deg > 32) {
        for (int k = beg + 32 + lane; k < end; k += 32) {
            int d2 = g_csr_dst[k];
            float e = sn + g_d[d2];
            e = e > 0.f ? e : NEG_SLOPE * e;
            float mn = fmaxf(mx, e);
            den = den * __expf(mx - mn) + __expf(e - mn);
            mx = mn;
        }
    }
    {
        float mn = fmaxf(mx, ek);
        den = den * __expf(mx - mn) + ((lane < deg) ? __expf(ek - mn) : 0.f);
        mx = mn;
    }
#pragma unroll
    for (int o = 16; o > 0; o >>= 1) {
        float m2 = __shfl_xor_sync(0xffffffffu, mx, o);
        float d2 = __shfl_xor_sync(0xffffffffu, den, o);
        float mn = fmaxf(mx, m2);
        den = den * __expf(mx - mn) + d2 * __expf(m2 - mn);
        mx = mn;
    }
    float inv = (deg > 0) ? 1.0f / den : 0.0f;
    float attk = (lane < deg) ? __expf(ek - mx) * inv : 0.0f;

    float2 acc = make_float2(0.f, 0.f);
    int cnt = min(deg, 32);
    for (int t = 0; t < cnt; t += 8) {
        int dd[8]; float aa[8]; float2 hh[8];
#pragma unroll
        for (int u = 0; u < 8; ++u) {
            dd[u] = __shfl_sync(0xffffffffu, dk, t + u);
            aa[u] = __shfl_sync(0xffffffffu, attk, t + u);
        }
#pragma unroll
        for (int u = 0; u < 8; ++u)
            hh[u] = *(const float2*)(g_Hw1 + dd[u] * HID + lane * 2);
#pragma unroll
        for (int u = 0; u < 8; ++u) {
            acc.x = fmaf(aa[u], hh[u].x, acc.x);
            acc.y = fmaf(aa[u], hh[u].y, acc.y);
        }
    }
    for (int base = beg + 32; base < end; base += 32) {
        int k = base + lane;
        int dk2 = 0; float att2 = 0.f;
        if (k < end) {
            dk2 = g_csr_dst[k];
            float e = sn + g_d[dk2];
            e = e > 0.f ? e : NEG_SLOPE * e;
            att2 = __expf(e - mx) * inv;
        }
        int cnt2 = min(32, end - base);
        for (int t = 0; t < cnt2; t += 8) {
            int dd[8]; float aa[8]; float2 hh[8];
#pragma unroll
            for (int u = 0; u < 8; ++u) {
                dd[u] = __shfl_sync(0xffffffffu, dk2, t + u);
                aa[u] = __shfl_sync(0xffffffffu, att2, t + u);
            }
#pragma unroll
            for (int u = 0; u < 8; ++u)
                hh[u] = *(const float2*)(g_Hw1 + dd[u] * HID + lane * 2);
#pragma unroll
            for (int u = 0; u < 8; ++u) {
                acc.x = fmaf(aa[u], hh[u].x, acc.x);
                acc.y = fmaf(aa[u], hh[u].y, acc.y);
            }
        }
    }
    // ELU -> hidden (lane holds dims 2*lane, 2*lane+1)
    acc.x = acc.x > 0.f ? acc.x : expm1f(acc.x);
    acc.y = acc.y > 0.f ? acc.y : expm1f(acc.y);

    // fused gemm2: out[c=lane] = sum_k hidden[k] * W2[k][c]
    float o2 = 0.f;
#pragma unroll
    for (int k = 0; k < 32; ++k) {
        float hx = __shfl_sync(0xffffffffu, acc.x, k);
        float hy = __shfl_sync(0xffffffffu, acc.y, k);
        o2 = fmaf(hx, W2s[(2 * k) * CLS + lane], o2);
        o2 = fmaf(hy, W2s[(2 * k + 1) * CLS + lane], o2);
    }
    g_Hw2[n * CLS + lane] = o2;

    // fused layer-2 scores -> separate buffers
    float sp = o2 * A2s[lane];
    float dp = o2 * A2s[CLS + lane];
#pragma unroll
    for (int o = 16; o > 0; o >>= 1) {
        sp += __shfl_down_sync(0xffffffffu, sp, o);
        dp += __shfl_down_sync(0xffffffffu, dp, o);
    }
    if (lane == 0) { g_s2[n] = sp; g_d2[n] = dp; }
}

// ================= layer-2 softagg + log_softmax =============================
__global__ void k_softagg32(float* __restrict__ out) {
    int n = blockIdx.x * 8 + (threadIdx.x >> 5);
    int lane = threadIdx.x & 31;
    int beg = seg_beg(n), end = seg_end(n);
    int deg = end - beg;
    float sn = g_s2[n];

    int dk = 0; float ek = -1e30f;
    if (lane < deg) {
        dk = g_csr_dst[beg + lane];
        float e = sn + g_d2[dk];
        ek = e > 0.f ? e : NEG_SLOPE * e;
    }

    float mx = -1e30f, den = 0.f;
    if (deg > 32) {
        for (int k = beg + 32 + lane; k < end; k += 32) {
            int d2 = g_csr_dst[k];
            float e = sn + g_d2[d2];
            e = e > 0.f ? e : NEG_SLOPE * e;
            float mn = fmaxf(mx, e);
            den = den * __expf(mx - mn) + __expf(e - mn);
            mx = mn;
        }
    }
    {
        float mn = fmaxf(mx, ek);
        den = den * __expf(mx - mn) + ((lane < deg) ? __expf(ek - mn) : 0.f);
        mx = mn;
    }
#pragma unroll
    for (int o = 16; o > 0; o >>= 1) {
        float m2 = __shfl_xor_sync(0xffffffffu, mx, o);
        float d2 = __shfl_xor_sync(0xffffffffu, den, o);
        float mn = fmaxf(mx, m2);
        den = den * __expf(mx - mn) + d2 * __expf(m2 - mn);
        mx = mn;
    }
    float inv = (deg > 0) ? 1.0f / den : 0.0f;
    float attk = (lane < deg) ? __expf(ek - mx) * inv : 0.0f;

    float acc = 0.f;
    int cnt = min(deg, 32);
    for (int t = 0; t < cnt; t += 8) {
        int dd[8]; float aa[8]; float hh[8];
#pragma unroll
        for (int u = 0; u < 8; ++u) {
            dd[u] = __shfl_sync(0xffffffffu, dk, t + u);
            aa[u] = __shfl_sync(0xffffffffu, attk, t + u);
        }
#pragma unroll
        for (int u = 0; u < 8; ++u)
            hh[u] = g_Hw2[dd[u] * CLS + lane];
#pragma unroll
        for (int u = 0; u < 8; ++u)
            acc = fmaf(aa[u], hh[u], acc);
    }
    for (int base = beg + 32; base < end; base += 32) {
        int k = base + lane;
        int dk2 = 0; float att2 = 0.f;
        if (k < end) {
            dk2 = g_csr_dst[k];
            float e = sn + g_d2[dk2];
            e = e > 0.f ? e : NEG_SLOPE * e;
            att2 = __expf(e - mx) * inv;
        }
        int cnt2 = min(32, end - base);
        for (int t = 0; t < cnt2; t += 8) {
            int dd[8]; float aa[8]; float hh[8];
#pragma unroll
            for (int u = 0; u < 8; ++u) {
                dd[u] = __shfl_sync(0xffffffffu, dk2, t + u);
                aa[u] = __shfl_sync(0xffffffffu, att2, t + u);
            }
#pragma unroll
            for (int u = 0; u < 8; ++u)
                hh[u] = g_Hw2[dd[u] * CLS + lane];
#pragma unroll
            for (int u = 0; u < 8; ++u)
                acc = fmaf(aa[u], hh[u], acc);
        }
    }
    float m2 = acc;
#pragma unroll
    for (int o = 16; o > 0; o >>= 1) m2 = fmaxf(m2, __shfl_xor_sync(0xffffffffu, m2, o));
    float ex = __expf(acc - m2);
    float sm = ex;
#pragma unroll
    for (int o = 16; o > 0; o >>= 1) sm += __shfl_xor_sync(0xffffffffu, sm, o);
    out[n * CLS + lane] = acc - m2 - __logf(sm);
}

// ================= launch ====================================================
extern "C" void kernel_launch(void* const* d_in, const int* in_sizes, int n_in,
                              void* d_out, int out_size) {
    const float* X  = (const float*)d_in[0];
    const int*   EI = (const int*)d_in[1];
    const float* W1 = (const float*)d_in[2];
    const float* W2 = (const float*)d_in[3];
    const float* A1 = (const float*)d_in[4];
    const float* A2 = (const float*)d_in[5];
    float* out = (float*)d_out;

    cudaFuncSetAttribute(k_gemm1_mma,
                         cudaFuncAttributeMaxDynamicSharedMemorySize, GEMM1_SMEM);

    const int T = 256;
    int g_nodes = (N_NODES + T - 1) / T;
    int g_edges = (N_EDGES + T - 1) / T;

    k_init_pack<<<g_nodes, T>>>(W1);
    k_count<<<g_edges, T>>>(EI);
    k_scan1<<<NBLK_SCAN, 256>>>();
    k_scan2<<<1, 512>>>();
    k_fill<<<g_edges, T>>>(EI);

    k_gemm1_mma<<<(N_NODES + BM - 1) / BM, 256, GEMM1_SMEM>>>(X, A1);
    k_softagg64g2<<<N_NODES / 8, 256>>>(W2, A2);
    k_softagg32<<<N_NODES / 8, 256>>>(out);
}